// round 12
// baseline (speedup 1.0000x reference)
#include <cuda_runtime.h>
#include <cuda_bf16.h>
#include <mma.h>
#include <cstdint>

using namespace nvcuda;

#define NB 8
#define NSEQ 1024
#define NH 8
#define HD 64
#define CDIM 512

__device__ float g_q[NB*NH*NSEQ*HD];
__device__ float g_k[NB*NH*NSEQ*HD];
__device__ float g_v[NB*NH*NSEQ*HD];
__device__ float g_s[(size_t)NB*NH*NSEQ*NSEQ];   // 256 MB: exp(scale*dots)
__device__ float g_part[NB*NH*8*NSEQ];           // per-(z, n-tile) row sums of exp
__device__ float g_oh[NB*NSEQ*CDIM];

#define EPI_QKV  0
#define EPI_DOTS 1
#define EPI_OUT  3

using FragA  = wmma::fragment<wmma::matrix_a, 16, 16, 16, __nv_bfloat16, wmma::row_major>;
using FragBR = wmma::fragment<wmma::matrix_b, 16, 16, 16, __nv_bfloat16, wmma::row_major>;
using FragBC = wmma::fragment<wmma::matrix_b, 16, 16, 16, __nv_bfloat16, wmma::col_major>;
using FragC  = wmma::fragment<wmma::accumulator, 16, 16, 16, float>;

__device__ __forceinline__ void split4(const float4 v, uint2& hi, uint2& lo) {
    __nv_bfloat16 hx = __float2bfloat16(v.x), hy = __float2bfloat16(v.y);
    __nv_bfloat16 hz = __float2bfloat16(v.z), hw = __float2bfloat16(v.w);
    __nv_bfloat16 lx = __float2bfloat16(v.x - __bfloat162float(hx));
    __nv_bfloat16 ly = __float2bfloat16(v.y - __bfloat162float(hy));
    __nv_bfloat16 lz = __float2bfloat16(v.z - __bfloat162float(hz));
    __nv_bfloat16 lw = __float2bfloat16(v.w - __bfloat162float(hw));
    __nv_bfloat162 h0{hx, hy}, h1{hz, hw}, l0{lx, ly}, l1{lz, lw};
    hi.x = *reinterpret_cast<unsigned int*>(&h0); hi.y = *reinterpret_cast<unsigned int*>(&h1);
    lo.x = *reinterpret_cast<unsigned int*>(&l0); lo.y = *reinterpret_cast<unsigned int*>(&l1);
}

// ---------------------------------------------------------------------------
// 3-term bf16-split wmma GEMM (proven round-11 mainloop).
//  EPI_QKV: scatter q/k/v.  EPI_DOTS: writes exp(0.125*dot) + row partials.
//  EPI_OUT: direct store.
// ---------------------------------------------------------------------------
template<int EPI, int KD, int LDA_, int LDB_, bool TRANSB, int BN>
__global__ __launch_bounds__(256, 2)
void tgemm(const float* __restrict__ Ain, const float* __restrict__ Bin,
           float* __restrict__ Cout)
{
    constexpr int BM = 128, BK = 32, KT = KD / BK;
    constexpr int FN = BN / 32;
    constexpr int WN = BN / 2;
    constexpr int LDAS = 40;
    constexpr int A_STG = BM * LDAS;
    constexpr int LDBS = TRANSB ? 40 : (BN + 8);
    constexpr int B_STG = TRANSB ? (BN * 40) : (BK * (BN + 8));
    constexpr int NB4 = BN / 32;

    extern __shared__ __align__(128) __nv_bfloat16 sm[];
    __nv_bfloat16* AsH = sm;
    __nv_bfloat16* AsL = sm + 2*A_STG;
    __nv_bfloat16* BsH = sm + 4*A_STG;
    __nv_bfloat16* BsL = sm + 4*A_STG + 2*B_STG;

    const int t   = threadIdx.x;
    const int wid = t >> 5;
    const int wm  = wid & 3, wn = wid >> 2;
    const int m0  = blockIdx.y * BM;
    const int n0  = blockIdx.x * BN;
    const int z   = blockIdx.z;

    const float* Ap;
    const float* Bp;
    if      constexpr (EPI == EPI_QKV)  { Ap = Ain;                     Bp = Bin; }
    else if constexpr (EPI == EPI_DOTS) { Ap = g_q + (size_t)z*NSEQ*HD; Bp = g_k + (size_t)z*NSEQ*HD; }
    else                                { Ap = g_oh;                    Bp = Bin; }

    float4 rA[4], rB[NB4];

    auto fetchA = [&](int k0) {
        #pragma unroll
        for (int i = 0; i < 4; i++) {
            const int idx = t + i*256;
            const int row = idx >> 3, k4 = (idx & 7) * 4;
            rA[i] = *reinterpret_cast<const float4*>(Ap + (size_t)(m0 + row) * LDA_ + k0 + k4);
        }
    };
    auto fetchB = [&](int k0) {
        #pragma unroll
        for (int i = 0; i < NB4; i++) {
            const int idx = t + i*256;
            if constexpr (TRANSB) {
                const int row = idx >> 3, k4 = (idx & 7) * 4;
                rB[i] = *reinterpret_cast<const float4*>(Bp + (size_t)(n0 + row) * LDB_ + k0 + k4);
            } else {
                constexpr int R4 = BN / 4;
                const int row = idx / R4, n4 = (idx % R4) * 4;
                rB[i] = *reinterpret_cast<const float4*>(Bp + (size_t)(k0 + row) * LDB_ + n0 + n4);
            }
        }
    };
    auto stage = [&](int st) {
        __nv_bfloat16* ah = AsH + st*A_STG;
        __nv_bfloat16* al = AsL + st*A_STG;
        #pragma unroll
        for (int i = 0; i < 4; i++) {
            const int idx = t + i*256;
            const int row = idx >> 3, k4 = (idx & 7) * 4;
            uint2 hi, lo; split4(rA[i], hi, lo);
            *reinterpret_cast<uint2*>(ah + row*LDAS + k4) = hi;
            *reinterpret_cast<uint2*>(al + row*LDAS + k4) = lo;
        }
        __nv_bfloat16* bh = BsH + st*B_STG;
        __nv_bfloat16* bl = BsL + st*B_STG;
        #pragma unroll
        for (int i = 0; i < NB4; i++) {
            const int idx = t + i*256;
            uint2 hi, lo; split4(rB[i], hi, lo);
            if constexpr (TRANSB) {
                const int row = idx >> 3, k4 = (idx & 7) * 4;
                *reinterpret_cast<uint2*>(bh + row*LDBS + k4) = hi;
                *reinterpret_cast<uint2*>(bl + row*LDBS + k4) = lo;
            } else {
                constexpr int R4 = BN / 4;
                const int row = idx / R4, n4 = (idx % R4) * 4;
                *reinterpret_cast<uint2*>(bh + row*LDBS + n4) = hi;
                *reinterpret_cast<uint2*>(bl + row*LDBS + n4) = lo;
            }
        }
    };

    FragC acc[2][FN];
    #pragma unroll
    for (int i = 0; i < 2; i++)
        #pragma unroll
        for (int j = 0; j < FN; j++) wmma::fill_fragment(acc[i][j], 0.f);

    fetchA(0); fetchB(0);
    stage(0);
    __syncthreads();

    for (int kt = 0; kt < KT; kt++) {
        const int st = kt & 1;
        if (kt + 1 < KT) { fetchA((kt+1)*BK); fetchB((kt+1)*BK); }

        const __nv_bfloat16* ah = AsH + st*A_STG;
        const __nv_bfloat16* al = AsL + st*A_STG;
        const __nv_bfloat16* bh = BsH + st*B_STG;
        const __nv_bfloat16* bl = BsL + st*B_STG;

        #pragma unroll
        for (int ks = 0; ks < 2; ks++) {
            FragA fah[2], fal[2];
            #pragma unroll
            for (int im = 0; im < 2; im++) {
                const int ro = (wm*32 + im*16)*LDAS + ks*16;
                wmma::load_matrix_sync(fah[im], ah + ro, LDAS);
                wmma::load_matrix_sync(fal[im], al + ro, LDAS);
            }
            if constexpr (TRANSB) {
                FragBC fbh[FN], fbl[FN];
                #pragma unroll
                for (int in_ = 0; in_ < FN; in_++) {
                    const int bo = (wn*WN + in_*16)*LDBS + ks*16;
                    wmma::load_matrix_sync(fbh[in_], bh + bo, LDBS);
                    wmma::load_matrix_sync(fbl[in_], bl + bo, LDBS);
                }
                #pragma unroll
                for (int im = 0; im < 2; im++)
                    #pragma unroll
                    for (int in_ = 0; in_ < FN; in_++) {
                        wmma::mma_sync(acc[im][in_], fah[im], fbh[in_], acc[im][in_]);
                        wmma::mma_sync(acc[im][in_], fal[im], fbh[in_], acc[im][in_]);
                        wmma::mma_sync(acc[im][in_], fah[im], fbl[in_], acc[im][in_]);
                    }
            } else {
                FragBR fbh[FN], fbl[FN];
                #pragma unroll
                for (int in_ = 0; in_ < FN; in_++) {
                    const int bo = (ks*16)*LDBS + wn*WN + in_*16;
                    wmma::load_matrix_sync(fbh[in_], bh + bo, LDBS);
                    wmma::load_matrix_sync(fbl[in_], bl + bo, LDBS);
                }
                #pragma unroll
                for (int im = 0; im < 2; im++)
                    #pragma unroll
                    for (int in_ = 0; in_ < FN; in_++) {
                        wmma::mma_sync(acc[im][in_], fah[im], fbh[in_], acc[im][in_]);
                        wmma::mma_sync(acc[im][in_], fal[im], fbh[in_], acc[im][in_]);
                        wmma::mma_sync(acc[im][in_], fah[im], fbl[in_], acc[im][in_]);
                    }
            }
        }

        if (kt + 1 < KT) stage(st ^ 1);
        __syncthreads();
    }

    if constexpr (EPI == EPI_DOTS) {
        // stage -> exp -> g_s, plus deterministic row partial sums
        float* stg = reinterpret_cast<float*>(sm);     // 128 x 132 fp32 (67584 B)
        #pragma unroll
        for (int im = 0; im < 2; im++)
            #pragma unroll
            for (int in_ = 0; in_ < FN; in_++)
                wmma::store_matrix_sync(&stg[(wm*32 + im*16)*132 + wn*WN + in_*16],
                                        acc[im][in_], 132, wmma::mem_row_major);
        __syncthreads();
        const int r = t >> 1, c0 = (t & 1) * 64;
        float ssum = 0.f;
        float* grow = g_s + ((size_t)z << 20) + (size_t)(m0 + r)*NSEQ + n0 + c0;
        #pragma unroll
        for (int u = 0; u < 64; u += 4) {
            float4 v4 = *reinterpret_cast<float4*>(&stg[r*132 + c0 + u]);
            v4.x = __expf(v4.x*0.125f); v4.y = __expf(v4.y*0.125f);
            v4.z = __expf(v4.z*0.125f); v4.w = __expf(v4.w*0.125f);
            ssum += v4.x + v4.y + v4.z + v4.w;
            *reinterpret_cast<float4*>(grow + u) = v4;
        }
        ssum += __shfl_xor_sync(0xffffffffu, ssum, 1);
        if ((t & 1) == 0)
            g_part[((size_t)(z*8 + blockIdx.x) << 10) + m0 + r] = ssum;
        return;
    }

    // direct-to-global epilogue (QKV / OUT)
    #pragma unroll
    for (int im = 0; im < 2; im++) {
        const int row0 = m0 + wm*32 + im*16;
        #pragma unroll
        for (int in_ = 0; in_ < FN; in_++) {
            const int c0 = n0 + wn*WN + in_*16;
            if constexpr (EPI == EPI_QKV) {
                const int part = c0 >> 9, h = (c0 & 511) >> 6, d = c0 & 63;
                const int b = row0 >> 10, nr = row0 & 1023;
                float* base = (part == 0) ? g_q : (part == 1) ? g_k : g_v;
                wmma::store_matrix_sync(base + (((size_t)(b*NH + h))*NSEQ + nr)*HD + d,
                                        acc[im][in_], HD, wmma::mem_row_major);
            } else {
                wmma::store_matrix_sync(Cout + (size_t)row0*CDIM + c0,
                                        acc[im][in_], CDIM, wmma::mem_row_major);
            }
        }
    }
}

// ---------------------------------------------------------------------------
// Fused softmax-normalize + head remix + LayerNorm + PV.
// CTA = (b, 32-row i-tile); all 8 heads accumulated; j-tiles of 64.
// smem: E[32][64][9] fp32 (e -> cg in place), V hi/lo [64][72], A hi/lo [32][72],
//       rS[8][32], W[64], gamma/beta.
// ---------------------------------------------------------------------------
#define IT 32
#define JT 64
#define FUSED_SMEM 102784

__global__ __launch_bounds__(256, 2)
void remix_ln_pv(const float* __restrict__ W,
                 const float* __restrict__ gamma,
                 const float* __restrict__ beta)
{
    extern __shared__ __align__(128) char smc[];
    float*          Ebuf = reinterpret_cast<float*>(smc);                 // 73728 B
    __nv_bfloat16*  Vhs  = reinterpret_cast<__nv_bfloat16*>(smc + 73728); // 9216 B
    __nv_bfloat16*  Vls  = reinterpret_cast<__nv_bfloat16*>(smc + 82944); // 9216 B
    __nv_bfloat16*  Ahs  = reinterpret_cast<__nv_bfloat16*>(smc + 92160); // 4608 B
    __nv_bfloat16*  Als  = reinterpret_cast<__nv_bfloat16*>(smc + 96768); // 4608 B
    float*          rSb  = reinterpret_cast<float*>(smc + 101376);        // 1024 B
    float*          w_s  = reinterpret_cast<float*>(smc + 102400);        // 256 B
    float*          gm   = reinterpret_cast<float*>(smc + 102656);        // 32 B
    float*          bt   = reinterpret_cast<float*>(smc + 102688);        // 32 B

    const int t    = threadIdx.x;
    const int wid  = t >> 5, lane = t & 31;
    const int wi   = wid >> 2, wd = wid & 3;      // warp patch (wi*16 i, wd*16 d)
    const int it0  = blockIdx.x * IT;
    const int b    = blockIdx.y;

    if (t < 64) w_s[t] = W[t];
    else if (t < 72) gm[t-64] = gamma[t-64];
    else if (t < 80) bt[t-72] = beta[t-72];

    // rS[h][i] = 1 / sum_nt g_part[b*8+h][nt][it0+i]
    {
        const int h = t >> 5, i = t & 31;
        const float* pp = g_part + (((size_t)(b*NH + h)) << 13) + it0 + i;
        float s = 0.f;
        #pragma unroll
        for (int nt = 0; nt < 8; nt++) s += pp[nt*1024];
        rSb[h*IT + i] = 1.f / s;
    }
    __syncthreads();

    FragC acc[8];
    #pragma unroll
    for (int g = 0; g < 8; g++) wmma::fill_fragment(acc[g], 0.f);

    for (int jt = 0; jt < NSEQ/JT; jt++) {
        const int j0 = jt * JT;

        // load e for all 8 heads, scale by rS -> p, store E[i][j][h] (stride 9)
        #pragma unroll
        for (int rr = 0; rr < 32; rr++) {
            const int row = wid*32 + rr;          // 0..255
            const int h = row >> 5, i = row & 31;
            const float* src = g_s + (((size_t)(b*NH + h)) << 20)
                             + (size_t)(it0 + i)*NSEQ + j0;
            const float s = rSb[h*IT + i];
            Ebuf[(i*JT + lane)*9 + h]      = src[lane]      * s;
            Ebuf[(i*JT + lane + 32)*9 + h] = src[lane + 32] * s;
        }
        __syncthreads();

        // remix + LN (in place: p -> cg = (mix - mu)*rstd)
        #pragma unroll
        for (int u = 0; u < 8; u++) {
            const int q = u*256 + t;               // position = i*64 + j
            float* ePos = Ebuf + 9*q;
            float p[8];
            #pragma unroll
            for (int h = 0; h < 8; h++) p[h] = ePos[h];
            float mix[8], mean = 0.f;
            #pragma unroll
            for (int g = 0; g < 8; g++) {
                float m = 0.f;
                #pragma unroll
                for (int h = 0; h < 8; h++) m += p[h] * w_s[h*8 + g];
                mix[g] = m; mean += m;
            }
            mean *= 0.125f;
            float var = 0.f;
            #pragma unroll
            for (int g = 0; g < 8; g++) { const float d = mix[g] - mean; var += d*d; }
            var *= 0.125f;
            const float rstd = rsqrtf(var + 1e-5f);
            #pragma unroll
            for (int g = 0; g < 8; g++) ePos[g] = (mix[g] - mean) * rstd;
        }
        __syncthreads();

        #pragma unroll
        for (int g = 0; g < 8; g++) {
            // stage attn_g (bf16 hi/lo)
            const float gg = gm[g], bb = bt[g];
            #pragma unroll
            for (int u = 0; u < 8; u++) {
                const int q = u*256 + t;
                const int i = q >> 6, j = q & 63;
                const float a = Ebuf[9*q + g] * gg + bb;
                const __nv_bfloat16 h16 = __float2bfloat16(a);
                const __nv_bfloat16 l16 = __float2bfloat16(a - __bfloat162float(h16));
                Ahs[i*72 + j] = h16;
                Als[i*72 + j] = l16;
            }
            // stage v_g tile (fp32 -> bf16 hi/lo)
            {
                const int jr = t >> 2, d0 = (t & 3) * 16;
                const float* vsrc = g_v + ((size_t)(b*NH + g))*(NSEQ*HD)
                                  + (size_t)(j0 + jr)*HD + d0;
                __nv_bfloat16* vh = Vhs + jr*72 + d0;
                __nv_bfloat16* vl = Vls + jr*72 + d0;
                #pragma unroll
                for (int u = 0; u < 4; u++) {
                    const float4 v4 = *reinterpret_cast<const float4*>(vsrc + u*4);
                    uint2 hi, lo; split4(v4, hi, lo);
                    *reinterpret_cast<uint2*>(vh + u*4) = hi;
                    *reinterpret_cast<uint2*>(vl + u*4) = lo;
                }
            }
            __syncthreads();
            // mma: warp patch 16i x 16d, k over 64 j
            #pragma unroll
            for (int ks = 0; ks < 4; ks++) {
                FragA fa_h, fa_l;
                FragBR fb_h, fb_l;
                wmma::load_matrix_sync(fa_h, Ahs + (wi*16)*72 + ks*16, 72);
                wmma::load_matrix_sync(fa_l, Als + (wi*16)*72 + ks*16, 72);
                wmma::load_matrix_sync(fb_h, Vhs + (ks*16)*72 + wd*16, 72);
                wmma::load_matrix_sync(fb_l, Vls + (ks*16)*72 + wd*16, 72);
                wmma::mma_sync(acc[g], fa_h, fb_h, acc[g]);
                wmma::mma_sync(acc[g], fa_l, fb_h, acc[g]);
                wmma::mma_sync(acc[g], fa_h, fb_l, acc[g]);
            }
            __syncthreads();
        }
    }

    // epilogue -> g_oh
    #pragma unroll
    for (int g = 0; g < 8; g++) {
        float* dst = g_oh + ((size_t)(b*NSEQ + it0 + wi*16))*CDIM + g*HD + wd*16;
        wmma::store_matrix_sync(dst, acc[g], CDIM, wmma::mem_row_major);
    }
}

__global__ void bias_add_k(float* __restrict__ out, const float* __restrict__ bias)
{
    const int i = blockIdx.x * blockDim.x + threadIdx.x;
    out[i] += bias[i & (CDIM-1)];
}

// ---------------------------------------------------------------------------
extern "C" void kernel_launch(void* const* d_in, const int* in_sizes, int n_in,
                              void* d_out, int out_size)
{
    const float* x      = (const float*)d_in[0];
    const float* w_qkv  = (const float*)d_in[1];
    const float* reattn = (const float*)d_in[2];
    const float* gamma  = (const float*)d_in[3];
    const float* beta   = (const float*)d_in[4];
    const float* w_out  = (const float*)d_in[5];
    const float* b_out  = (const float*)d_in[6];
    float* out = (float*)d_out;

    constexpr int SM_QKV  = 2*(4*128*40 + 4*32*136);   // 75776
    constexpr int SM_DOTS = 2*(4*128*40 + 4*128*40);   // 81920 (>= 67584 staging)
    constexpr int SM_OUT  = SM_QKV;

    cudaFuncSetAttribute(tgemm<EPI_QKV, 512, 512, 1536, false, 128>, cudaFuncAttributeMaxDynamicSharedMemorySize, SM_QKV);
    cudaFuncSetAttribute(tgemm<EPI_DOTS, 64, 64, 64, true, 128>,     cudaFuncAttributeMaxDynamicSharedMemorySize, SM_DOTS);
    cudaFuncSetAttribute(tgemm<EPI_OUT, 512, 512, 512, false, 128>,  cudaFuncAttributeMaxDynamicSharedMemorySize, SM_OUT);
    cudaFuncSetAttribute(remix_ln_pv, cudaFuncAttributeMaxDynamicSharedMemorySize, FUSED_SMEM);

    // 1) qkv = x @ w_qkv -> scatter g_q/g_k/g_v
    tgemm<EPI_QKV, 512, 512, 1536, false, 128>
        <<<dim3(12, 64, 1), 256, SM_QKV>>>(x, w_qkv, nullptr);
    // 2) e = exp(scale * q@k^T) -> g_s, row partial sums -> g_part
    tgemm<EPI_DOTS, 64, 64, 64, true, 128>
        <<<dim3(8, 8, 64), 256, SM_DOTS>>>(nullptr, nullptr, nullptr);
    // 3) fused: normalize + remix + LN + PV -> g_oh
    remix_ln_pv<<<dim3(NSEQ/IT, NB), 256, FUSED_SMEM>>>(reattn, gamma, beta);
    // 4) out = g_oh @ w_out ; then + b_out
    tgemm<EPI_OUT, 512, 512, 512, false, 128>
        <<<dim3(4, 64, 1), 256, SM_OUT>>>(nullptr, w_out, out);
    bias_add_k<<<(8192*512)/256, 256>>>(out, b_out);
}

// round 13
// speedup vs baseline: 1.0276x; 1.0276x over previous
#include <cuda_runtime.h>
#include <cuda_bf16.h>
#include <mma.h>
#include <cstdint>

using namespace nvcuda;

#define NB 8
#define NSEQ 1024
#define NH 8
#define HD 64
#define CDIM 512

__device__ float g_q[NB*NH*NSEQ*HD];
__device__ float g_k[NB*NH*NSEQ*HD];
__device__ __nv_bfloat16 v_hi[NB*NH*NSEQ*HD];
__device__ __nv_bfloat16 v_lo[NB*NH*NSEQ*HD];
__device__ float g_s[(size_t)NB*NH*NSEQ*NSEQ];   // 256 MB: exp(scale*dots)
__device__ float g_part[NB*NH*8*NSEQ];           // per-(z, n-tile) row sums of exp
__device__ float g_oh[NB*NSEQ*CDIM];

#define EPI_QKV  0
#define EPI_DOTS 1
#define EPI_OUT  3

using FragA  = wmma::fragment<wmma::matrix_a, 16, 16, 16, __nv_bfloat16, wmma::row_major>;
using FragBR = wmma::fragment<wmma::matrix_b, 16, 16, 16, __nv_bfloat16, wmma::row_major>;
using FragBC = wmma::fragment<wmma::matrix_b, 16, 16, 16, __nv_bfloat16, wmma::col_major>;
using FragC  = wmma::fragment<wmma::accumulator, 16, 16, 16, float>;

__device__ __forceinline__ void split4(const float4 v, uint2& hi, uint2& lo) {
    __nv_bfloat16 hx = __float2bfloat16(v.x), hy = __float2bfloat16(v.y);
    __nv_bfloat16 hz = __float2bfloat16(v.z), hw = __float2bfloat16(v.w);
    __nv_bfloat16 lx = __float2bfloat16(v.x - __bfloat162float(hx));
    __nv_bfloat16 ly = __float2bfloat16(v.y - __bfloat162float(hy));
    __nv_bfloat16 lz = __float2bfloat16(v.z - __bfloat162float(hz));
    __nv_bfloat16 lw = __float2bfloat16(v.w - __bfloat162float(hw));
    __nv_bfloat162 h0{hx, hy}, h1{hz, hw}, l0{lx, ly}, l1{lz, lw};
    hi.x = *reinterpret_cast<unsigned int*>(&h0); hi.y = *reinterpret_cast<unsigned int*>(&h1);
    lo.x = *reinterpret_cast<unsigned int*>(&l0); lo.y = *reinterpret_cast<unsigned int*>(&l1);
}

// ---------------------------------------------------------------------------
// 3-term bf16-split wmma GEMM (proven mainloop).
//  EPI_QKV: q/k direct stores; v -> bf16 hi/lo planes via smem stage.
//  EPI_DOTS: exp(0.125*dot) -> g_s + row partial sums (proven r12).
//  EPI_OUT: direct store.
// ---------------------------------------------------------------------------
template<int EPI, int KD, int LDA_, int LDB_, bool TRANSB, int BN>
__global__ __launch_bounds__(256, 2)
void tgemm(const float* __restrict__ Ain, const float* __restrict__ Bin,
           float* __restrict__ Cout)
{
    constexpr int BM = 128, BK = 32, KT = KD / BK;
    constexpr int FN = BN / 32;
    constexpr int WN = BN / 2;
    constexpr int LDAS = 40;
    constexpr int A_STG = BM * LDAS;
    constexpr int LDBS = TRANSB ? 40 : (BN + 8);
    constexpr int B_STG = TRANSB ? (BN * 40) : (BK * (BN + 8));
    constexpr int NB4 = BN / 32;

    extern __shared__ __align__(128) __nv_bfloat16 sm[];
    __nv_bfloat16* AsH = sm;
    __nv_bfloat16* AsL = sm + 2*A_STG;
    __nv_bfloat16* BsH = sm + 4*A_STG;
    __nv_bfloat16* BsL = sm + 4*A_STG + 2*B_STG;

    const int t   = threadIdx.x;
    const int wid = t >> 5;
    const int wm  = wid & 3, wn = wid >> 2;
    const int m0  = blockIdx.y * BM;
    const int n0  = blockIdx.x * BN;
    const int z   = blockIdx.z;

    const float* Ap;
    const float* Bp;
    if      constexpr (EPI == EPI_QKV)  { Ap = Ain;                     Bp = Bin; }
    else if constexpr (EPI == EPI_DOTS) { Ap = g_q + (size_t)z*NSEQ*HD; Bp = g_k + (size_t)z*NSEQ*HD; }
    else                                { Ap = g_oh;                    Bp = Bin; }

    float4 rA[4], rB[NB4];

    auto fetchA = [&](int k0) {
        #pragma unroll
        for (int i = 0; i < 4; i++) {
            const int idx = t + i*256;
            const int row = idx >> 3, k4 = (idx & 7) * 4;
            rA[i] = *reinterpret_cast<const float4*>(Ap + (size_t)(m0 + row) * LDA_ + k0 + k4);
        }
    };
    auto fetchB = [&](int k0) {
        #pragma unroll
        for (int i = 0; i < NB4; i++) {
            const int idx = t + i*256;
            if constexpr (TRANSB) {
                const int row = idx >> 3, k4 = (idx & 7) * 4;
                rB[i] = *reinterpret_cast<const float4*>(Bp + (size_t)(n0 + row) * LDB_ + k0 + k4);
            } else {
                constexpr int R4 = BN / 4;
                const int row = idx / R4, n4 = (idx % R4) * 4;
                rB[i] = *reinterpret_cast<const float4*>(Bp + (size_t)(k0 + row) * LDB_ + n0 + n4);
            }
        }
    };
    auto stage = [&](int st) {
        __nv_bfloat16* ah = AsH + st*A_STG;
        __nv_bfloat16* al = AsL + st*A_STG;
        #pragma unroll
        for (int i = 0; i < 4; i++) {
            const int idx = t + i*256;
            const int row = idx >> 3, k4 = (idx & 7) * 4;
            uint2 hi, lo; split4(rA[i], hi, lo);
            *reinterpret_cast<uint2*>(ah + row*LDAS + k4) = hi;
            *reinterpret_cast<uint2*>(al + row*LDAS + k4) = lo;
        }
        __nv_bfloat16* bh = BsH + st*B_STG;
        __nv_bfloat16* bl = BsL + st*B_STG;
        #pragma unroll
        for (int i = 0; i < NB4; i++) {
            const int idx = t + i*256;
            uint2 hi, lo; split4(rB[i], hi, lo);
            if constexpr (TRANSB) {
                const int row = idx >> 3, k4 = (idx & 7) * 4;
                *reinterpret_cast<uint2*>(bh + row*LDBS + k4) = hi;
                *reinterpret_cast<uint2*>(bl + row*LDBS + k4) = lo;
            } else {
                constexpr int R4 = BN / 4;
                const int row = idx / R4, n4 = (idx % R4) * 4;
                *reinterpret_cast<uint2*>(bh + row*LDBS + n4) = hi;
                *reinterpret_cast<uint2*>(bl + row*LDBS + n4) = lo;
            }
        }
    };

    FragC acc[2][FN];
    #pragma unroll
    for (int i = 0; i < 2; i++)
        #pragma unroll
        for (int j = 0; j < FN; j++) wmma::fill_fragment(acc[i][j], 0.f);

    fetchA(0); fetchB(0);
    stage(0);
    __syncthreads();

    for (int kt = 0; kt < KT; kt++) {
        const int st = kt & 1;
        if (kt + 1 < KT) { fetchA((kt+1)*BK); fetchB((kt+1)*BK); }

        const __nv_bfloat16* ah = AsH + st*A_STG;
        const __nv_bfloat16* al = AsL + st*A_STG;
        const __nv_bfloat16* bh = BsH + st*B_STG;
        const __nv_bfloat16* bl = BsL + st*B_STG;

        #pragma unroll
        for (int ks = 0; ks < 2; ks++) {
            FragA fah[2], fal[2];
            #pragma unroll
            for (int im = 0; im < 2; im++) {
                const int ro = (wm*32 + im*16)*LDAS + ks*16;
                wmma::load_matrix_sync(fah[im], ah + ro, LDAS);
                wmma::load_matrix_sync(fal[im], al + ro, LDAS);
            }
            if constexpr (TRANSB) {
                FragBC fbh[FN], fbl[FN];
                #pragma unroll
                for (int in_ = 0; in_ < FN; in_++) {
                    const int bo = (wn*WN + in_*16)*LDBS + ks*16;
                    wmma::load_matrix_sync(fbh[in_], bh + bo, LDBS);
                    wmma::load_matrix_sync(fbl[in_], bl + bo, LDBS);
                }
                #pragma unroll
                for (int im = 0; im < 2; im++)
                    #pragma unroll
                    for (int in_ = 0; in_ < FN; in_++) {
                        wmma::mma_sync(acc[im][in_], fah[im], fbh[in_], acc[im][in_]);
                        wmma::mma_sync(acc[im][in_], fal[im], fbh[in_], acc[im][in_]);
                        wmma::mma_sync(acc[im][in_], fah[im], fbl[in_], acc[im][in_]);
                    }
            } else {
                FragBR fbh[FN], fbl[FN];
                #pragma unroll
                for (int in_ = 0; in_ < FN; in_++) {
                    const int bo = (ks*16)*LDBS + wn*WN + in_*16;
                    wmma::load_matrix_sync(fbh[in_], bh + bo, LDBS);
                    wmma::load_matrix_sync(fbl[in_], bl + bo, LDBS);
                }
                #pragma unroll
                for (int im = 0; im < 2; im++)
                    #pragma unroll
                    for (int in_ = 0; in_ < FN; in_++) {
                        wmma::mma_sync(acc[im][in_], fah[im], fbh[in_], acc[im][in_]);
                        wmma::mma_sync(acc[im][in_], fal[im], fbh[in_], acc[im][in_]);
                        wmma::mma_sync(acc[im][in_], fah[im], fbl[in_], acc[im][in_]);
                    }
            }
        }

        if (kt + 1 < KT) stage(st ^ 1);
        __syncthreads();
    }

    if constexpr (EPI == EPI_DOTS) {
        // stage -> exp -> g_s, plus deterministic row partial sums (r12 proven)
        float* stg = reinterpret_cast<float*>(sm);     // 128 x 132 fp32
        #pragma unroll
        for (int im = 0; im < 2; im++)
            #pragma unroll
            for (int in_ = 0; in_ < FN; in_++)
                wmma::store_matrix_sync(&stg[(wm*32 + im*16)*132 + wn*WN + in_*16],
                                        acc[im][in_], 132, wmma::mem_row_major);
        __syncthreads();
        const int r = t >> 1, c0 = (t & 1) * 64;
        float ssum = 0.f;
        float* grow = g_s + ((size_t)z << 20) + (size_t)(m0 + r)*NSEQ + n0 + c0;
        #pragma unroll
        for (int u = 0; u < 64; u += 4) {
            float4 v4 = *reinterpret_cast<float4*>(&stg[r*132 + c0 + u]);
            v4.x = __expf(v4.x*0.125f); v4.y = __expf(v4.y*0.125f);
            v4.z = __expf(v4.z*0.125f); v4.w = __expf(v4.w*0.125f);
            ssum += v4.x + v4.y + v4.z + v4.w;
            *reinterpret_cast<float4*>(grow + u) = v4;
        }
        ssum += __shfl_xor_sync(0xffffffffu, ssum, 1);
        if ((t & 1) == 0)
            g_part[((size_t)(z*8 + blockIdx.x) << 10) + m0 + r] = ssum;
        return;
    }

    if constexpr (EPI == EPI_QKV) {
        if (n0 < 1024) {
            // q or k: direct frag stores (tile fully inside one part)
            #pragma unroll
            for (int im = 0; im < 2; im++) {
                const int row0 = m0 + wm*32 + im*16;
                #pragma unroll
                for (int in_ = 0; in_ < FN; in_++) {
                    const int c0 = n0 + wn*WN + in_*16;
                    const int part = c0 >> 9, h = (c0 & 511) >> 6, d = c0 & 63;
                    const int b = row0 >> 10, nr = row0 & 1023;
                    float* base = (part == 0) ? g_q : g_k;
                    wmma::store_matrix_sync(base + (((size_t)(b*NH + h))*NSEQ + nr)*HD + d,
                                            acc[im][in_], HD, wmma::mem_row_major);
                }
            }
        } else {
            // v: stage fp32 -> split to bf16 hi/lo planes
            float* stg = reinterpret_cast<float*>(sm);   // 128 x 136
            #pragma unroll
            for (int im = 0; im < 2; im++)
                #pragma unroll
                for (int in_ = 0; in_ < FN; in_++)
                    wmma::store_matrix_sync(&stg[(wm*32 + im*16)*136 + wn*WN + in_*16],
                                            acc[im][in_], 136, wmma::mem_row_major);
            __syncthreads();
            #pragma unroll
            for (int u = 0; u < 16; u++) {
                const int idx = t + u*256;                 // 4096 float4s
                const int lr = idx >> 5, lc4 = (idx & 31) * 4;
                const float4 v4 = *reinterpret_cast<float4*>(&stg[lr*136 + lc4]);
                const int col = (n0 - 1024) + lc4;
                const int h = col >> 6, d = col & 63;
                const int m = m0 + lr;
                const int b = m >> 10, nr = m & 1023;
                uint2 hi, lo; split4(v4, hi, lo);
                const size_t o = (((size_t)(b*NH + h)) << 16) + nr*HD + d;
                *reinterpret_cast<uint2*>(v_hi + o) = hi;
                *reinterpret_cast<uint2*>(v_lo + o) = lo;
            }
        }
        return;
    }

    // EPI_OUT: direct stores
    #pragma unroll
    for (int im = 0; im < 2; im++) {
        const int row0 = m0 + wm*32 + im*16;
        #pragma unroll
        for (int in_ = 0; in_ < FN; in_++) {
            const int c0 = n0 + wn*WN + in_*16;
            wmma::store_matrix_sync(Cout + (size_t)row0*CDIM + c0,
                                    acc[im][in_], CDIM, wmma::mem_row_major);
        }
    }
}

// ---------------------------------------------------------------------------
// Fused normalize + remix + LN + PV, warp-per-head.
// CTA = (b, 16-row i-tile) -> 512 CTAs, 8 warps = 8 heads.
// Per 64-wide j-tile: 3 block syncs total; per-warp smem panels for A/V.
// ---------------------------------------------------------------------------
#define FUSED_SMEM 86912

__global__ __launch_bounds__(256, 2)
void remix_ln_pv(const float* __restrict__ W,
                 const float* __restrict__ gamma,
                 const float* __restrict__ beta)
{
    extern __shared__ __align__(128) char smc[];
    float*          P  = reinterpret_cast<float*>(smc);                     // [16][577] f32
    __nv_bfloat16*  Ah = reinterpret_cast<__nv_bfloat16*>(smc + 36928);     // [8][16][24]
    __nv_bfloat16*  Al = reinterpret_cast<__nv_bfloat16*>(smc + 43072);
    __nv_bfloat16*  Vh = reinterpret_cast<__nv_bfloat16*>(smc + 49216);     // [8][16][72]
    __nv_bfloat16*  Vl = reinterpret_cast<__nv_bfloat16*>(smc + 67648);
    float*          rs = reinterpret_cast<float*>(smc + 86080);             // [8][16]
    float*          w_s= reinterpret_cast<float*>(smc + 86592);             // [64]
    float*          gm = reinterpret_cast<float*>(smc + 86848);             // [8]
    float*          bt = reinterpret_cast<float*>(smc + 86880);             // [8]

    const int t = threadIdx.x, g = t >> 5, lane = t & 31;
    const int it0 = blockIdx.x * 16;
    const int b = blockIdx.y;

    if (t < 64) w_s[t] = W[t];
    else if (t < 72) gm[t-64] = gamma[t-64];
    else if (t < 80) bt[t-72] = beta[t-72];
    if (t < 128) {
        const int h = t >> 4, i = t & 15;
        const float* pp = g_part + (((size_t)(b*NH + h)) << 13) + it0 + i;
        float s = 0.f;
        #pragma unroll
        for (int nt = 0; nt < 8; nt++) s += pp[nt << 10];
        rs[t] = 1.f / s;
    }
    __syncthreads();

    FragC acc[4];
    #pragma unroll
    for (int df = 0; df < 4; df++) wmma::fill_fragment(acc[df], 0.f);

    const float* esrc = g_s + (((size_t)(b*NH + g)) << 20) + (size_t)it0*NSEQ;
    const __nv_bfloat16* vhg = v_hi + (((size_t)(b*NH + g)) << 16);
    const __nv_bfloat16* vlg = v_lo + (((size_t)(b*NH + g)) << 16);

    for (int jt = 0; jt < 16; jt++) {
        const int j0 = jt * 64;

        // 1) stream own head's e tile, normalize, scatter into P
        #pragma unroll
        for (int u = 0; u < 8; u++) {
            const int r = u*2 + (lane >> 4);
            const int c4 = (lane & 15) * 4;
            const float4 e4 = *reinterpret_cast<const float4*>(esrc + (size_t)r*NSEQ + j0 + c4);
            const float s = rs[g*16 + r];
            float* pb = P + r*577 + c4*9 + g;
            pb[0] = e4.x*s; pb[9] = e4.y*s; pb[18] = e4.z*s; pb[27] = e4.w*s;
        }
        __syncthreads();

        // 2) remix + LN + gamma/beta, in place
        #pragma unroll
        for (int u = 0; u < 4; u++) {
            const int pos = t + u*256;
            const int i = pos >> 6, j = pos & 63;
            float* base = P + i*577 + j*9;
            float p[8];
            #pragma unroll
            for (int h = 0; h < 8; h++) p[h] = base[h];
            float mix[8], mean = 0.f;
            #pragma unroll
            for (int gg = 0; gg < 8; gg++) {
                float m = 0.f;
                #pragma unroll
                for (int h = 0; h < 8; h++) m += p[h] * w_s[h*8 + gg];
                mix[gg] = m; mean += m;
            }
            mean *= 0.125f;
            float var = 0.f;
            #pragma unroll
            for (int gg = 0; gg < 8; gg++) { const float d = mix[gg] - mean; var += d*d; }
            var *= 0.125f;
            const float rstd = rsqrtf(var + 1e-5f);
            #pragma unroll
            for (int gg = 0; gg < 8; gg++)
                base[gg] = (mix[gg] - mean) * rstd * gm[gg] + bt[gg];
        }
        __syncthreads();

        // 3) per k-step: warp-private A/V staging + mma (no block syncs)
        #pragma unroll
        for (int ks = 0; ks < 4; ks++) {
            uint4 vh4[4], vl4[4];
            #pragma unroll
            for (int u = 0; u < 4; u++) {
                const int idx = lane + u*32;
                const int jr = idx >> 3, d8 = (idx & 7) * 8;
                vh4[u] = *reinterpret_cast<const uint4*>(vhg + (size_t)(j0 + ks*16 + jr)*HD + d8);
                vl4[u] = *reinterpret_cast<const uint4*>(vlg + (size_t)(j0 + ks*16 + jr)*HD + d8);
            }
            // stage A panel (covers V-load latency)
            {
                const int ai = lane & 15, khalf = lane >> 4;
                #pragma unroll
                for (int u = 0; u < 8; u++) {
                    const int kk = khalf*8 + u;
                    const float a = P[ai*577 + (ks*16 + kk)*9 + g];
                    const __nv_bfloat16 h16 = __float2bfloat16(a);
                    const __nv_bfloat16 l16 = __float2bfloat16(a - __bfloat162float(h16));
                    Ah[g*384 + ai*24 + kk] = h16;
                    Al[g*384 + ai*24 + kk] = l16;
                }
            }
            #pragma unroll
            for (int u = 0; u < 4; u++) {
                const int idx = lane + u*32;
                const int jr = idx >> 3, d8 = (idx & 7) * 8;
                *reinterpret_cast<uint4*>(Vh + g*1152 + jr*72 + d8) = vh4[u];
                *reinterpret_cast<uint4*>(Vl + g*1152 + jr*72 + d8) = vl4[u];
            }
            __syncwarp();
            FragA fa_h, fa_l;
            wmma::load_matrix_sync(fa_h, Ah + g*384, 24);
            wmma::load_matrix_sync(fa_l, Al + g*384, 24);
            #pragma unroll
            for (int df = 0; df < 4; df++) {
                FragBR fb_h, fb_l;
                wmma::load_matrix_sync(fb_h, Vh + g*1152 + df*16, 72);
                wmma::load_matrix_sync(fb_l, Vl + g*1152 + df*16, 72);
                wmma::mma_sync(acc[df], fa_h, fb_h, acc[df]);
                wmma::mma_sync(acc[df], fa_l, fb_h, acc[df]);
                wmma::mma_sync(acc[df], fa_h, fb_l, acc[df]);
            }
            __syncwarp();
        }
        __syncthreads();   // before next jt overwrites P
    }

    float* dst = g_oh + ((size_t)(b*NSEQ + it0))*CDIM + g*HD;
    #pragma unroll
    for (int df = 0; df < 4; df++)
        wmma::store_matrix_sync(dst + df*16, acc[df], CDIM, wmma::mem_row_major);
}

__global__ void bias_add_k(float* __restrict__ out, const float* __restrict__ bias)
{
    const int i = blockIdx.x * blockDim.x + threadIdx.x;
    out[i] += bias[i & (CDIM-1)];
}

// ---------------------------------------------------------------------------
extern "C" void kernel_launch(void* const* d_in, const int* in_sizes, int n_in,
                              void* d_out, int out_size)
{
    const float* x      = (const float*)d_in[0];
    const float* w_qkv  = (const float*)d_in[1];
    const float* reattn = (const float*)d_in[2];
    const float* gamma  = (const float*)d_in[3];
    const float* beta   = (const float*)d_in[4];
    const float* w_out  = (const float*)d_in[5];
    const float* b_out  = (const float*)d_in[6];
    float* out = (float*)d_out;

    constexpr int SM_QKV  = 2*(4*128*40 + 4*32*136);   // 75776 (>= 69632 V staging)
    constexpr int SM_DOTS = 2*(4*128*40 + 4*128*40);   // 81920 (>= 67584 staging)
    constexpr int SM_OUT  = SM_QKV;

    cudaFuncSetAttribute(tgemm<EPI_QKV, 512, 512, 1536, false, 128>, cudaFuncAttributeMaxDynamicSharedMemorySize, SM_QKV);
    cudaFuncSetAttribute(tgemm<EPI_DOTS, 64, 64, 64, true, 128>,     cudaFuncAttributeMaxDynamicSharedMemorySize, SM_DOTS);
    cudaFuncSetAttribute(tgemm<EPI_OUT, 512, 512, 512, false, 128>,  cudaFuncAttributeMaxDynamicSharedMemorySize, SM_OUT);
    cudaFuncSetAttribute(remix_ln_pv, cudaFuncAttributeMaxDynamicSharedMemorySize, FUSED_SMEM);

    // 1) qkv = x @ w_qkv -> q/k fp32, v bf16 hi/lo planes
    tgemm<EPI_QKV, 512, 512, 1536, false, 128>
        <<<dim3(12, 64, 1), 256, SM_QKV>>>(x, w_qkv, nullptr);
    // 2) e = exp(scale * q@k^T) -> g_s, partials -> g_part
    tgemm<EPI_DOTS, 64, 64, 64, true, 128>
        <<<dim3(8, 8, 64), 256, SM_DOTS>>>(nullptr, nullptr, nullptr);
    // 3) fused normalize + remix + LN + PV -> g_oh
    remix_ln_pv<<<dim3(64, NB), 256, FUSED_SMEM>>>(reattn, gamma, beta);
    // 4) out = g_oh @ w_out ; then + b_out
    tgemm<EPI_OUT, 512, 512, 512, false, 128>
        <<<dim3(4, 64, 1), 256, SM_OUT>>>(nullptr, w_out, out);
    bias_add_k<<<(8192*512)/256, 256>>>(out, b_out);
}

// round 14
// speedup vs baseline: 1.3975x; 1.3599x over previous
#include <cuda_runtime.h>
#include <cuda_bf16.h>
#include <cuda_fp16.h>
#include <mma.h>
#include <cstdint>

using namespace nvcuda;

#define NB 8
#define NSEQ 1024
#define NH 8
#define HD 64
#define CDIM 512

__device__ float g_q[NB*NH*NSEQ*HD];
__device__ float g_k[NB*NH*NSEQ*HD];
__device__ __half v_hi[NB*NH*NSEQ*HD];
__device__ __half v_lo[NB*NH*NSEQ*HD];
__device__ float g_s[(size_t)NB*NH*NSEQ*NSEQ];   // 256 MB: exp(scale*dots)
__device__ float g_part[NB*NH*8*NSEQ];           // per-(z, n-tile) row sums of exp
__device__ __half g_a[(size_t)NB*NH*NSEQ*NSEQ];  // 128 MB: final attn (fp16)
__device__ float g_oh[NB*NSEQ*CDIM];

#define EPI_QKV  0
#define EPI_DOTS 1
#define EPI_OUT  3

using FragA  = wmma::fragment<wmma::matrix_a, 16, 16, 16, __nv_bfloat16, wmma::row_major>;
using FragBR = wmma::fragment<wmma::matrix_b, 16, 16, 16, __nv_bfloat16, wmma::row_major>;
using FragBC = wmma::fragment<wmma::matrix_b, 16, 16, 16, __nv_bfloat16, wmma::col_major>;
using FragC  = wmma::fragment<wmma::accumulator, 16, 16, 16, float>;
using HFragA = wmma::fragment<wmma::matrix_a, 16, 16, 16, __half, wmma::row_major>;
using HFragB = wmma::fragment<wmma::matrix_b, 16, 16, 16, __half, wmma::row_major>;

__device__ __forceinline__ void split4(const float4 v, uint2& hi, uint2& lo) {
    __nv_bfloat16 hx = __float2bfloat16(v.x), hy = __float2bfloat16(v.y);
    __nv_bfloat16 hz = __float2bfloat16(v.z), hw = __float2bfloat16(v.w);
    __nv_bfloat16 lx = __float2bfloat16(v.x - __bfloat162float(hx));
    __nv_bfloat16 ly = __float2bfloat16(v.y - __bfloat162float(hy));
    __nv_bfloat16 lz = __float2bfloat16(v.z - __bfloat162float(hz));
    __nv_bfloat16 lw = __float2bfloat16(v.w - __bfloat162float(hw));
    __nv_bfloat162 h0{hx, hy}, h1{hz, hw}, l0{lx, ly}, l1{lz, lw};
    hi.x = *reinterpret_cast<unsigned int*>(&h0); hi.y = *reinterpret_cast<unsigned int*>(&h1);
    lo.x = *reinterpret_cast<unsigned int*>(&l0); lo.y = *reinterpret_cast<unsigned int*>(&l1);
}

__device__ __forceinline__ void split4h(const float4 v, uint2& hi, uint2& lo) {
    __half hx = __float2half(v.x), hy = __float2half(v.y);
    __half hz = __float2half(v.z), hw = __float2half(v.w);
    __half lx = __float2half(v.x - __half2float(hx));
    __half ly = __float2half(v.y - __half2float(hy));
    __half lz = __float2half(v.z - __half2float(hz));
    __half lw = __float2half(v.w - __half2float(hw));
    __half2 h0{hx, hy}, h1{hz, hw}, l0{lx, ly}, l1{lz, lw};
    hi.x = *reinterpret_cast<unsigned int*>(&h0); hi.y = *reinterpret_cast<unsigned int*>(&h1);
    lo.x = *reinterpret_cast<unsigned int*>(&l0); lo.y = *reinterpret_cast<unsigned int*>(&l1);
}

// ---------------------------------------------------------------------------
// 3-term bf16-split wmma GEMM (proven r11-r13 mainloop).
//  EPI_QKV: q/k direct stores; v -> fp16 hi/lo planes via smem stage.
//  EPI_DOTS: exp(0.125*dot) -> g_s + row partial sums (proven).
//  EPI_OUT: direct store.
// ---------------------------------------------------------------------------
template<int EPI, int KD, int LDA_, int LDB_, bool TRANSB, int BN>
__global__ __launch_bounds__(256, 2)
void tgemm(const float* __restrict__ Ain, const float* __restrict__ Bin,
           float* __restrict__ Cout)
{
    constexpr int BM = 128, BK = 32, KT = KD / BK;
    constexpr int FN = BN / 32;
    constexpr int WN = BN / 2;
    constexpr int LDAS = 40;
    constexpr int A_STG = BM * LDAS;
    constexpr int LDBS = TRANSB ? 40 : (BN + 8);
    constexpr int B_STG = TRANSB ? (BN * 40) : (BK * (BN + 8));
    constexpr int NB4 = BN / 32;

    extern __shared__ __align__(128) __nv_bfloat16 sm[];
    __nv_bfloat16* AsH = sm;
    __nv_bfloat16* AsL = sm + 2*A_STG;
    __nv_bfloat16* BsH = sm + 4*A_STG;
    __nv_bfloat16* BsL = sm + 4*A_STG + 2*B_STG;

    const int t   = threadIdx.x;
    const int wid = t >> 5;
    const int wm  = wid & 3, wn = wid >> 2;
    const int m0  = blockIdx.y * BM;
    const int n0  = blockIdx.x * BN;
    const int z   = blockIdx.z;

    const float* Ap;
    const float* Bp;
    if      constexpr (EPI == EPI_QKV)  { Ap = Ain;                     Bp = Bin; }
    else if constexpr (EPI == EPI_DOTS) { Ap = g_q + (size_t)z*NSEQ*HD; Bp = g_k + (size_t)z*NSEQ*HD; }
    else                                { Ap = g_oh;                    Bp = Bin; }

    float4 rA[4], rB[NB4];

    auto fetchA = [&](int k0) {
        #pragma unroll
        for (int i = 0; i < 4; i++) {
            const int idx = t + i*256;
            const int row = idx >> 3, k4 = (idx & 7) * 4;
            rA[i] = *reinterpret_cast<const float4*>(Ap + (size_t)(m0 + row) * LDA_ + k0 + k4);
        }
    };
    auto fetchB = [&](int k0) {
        #pragma unroll
        for (int i = 0; i < NB4; i++) {
            const int idx = t + i*256;
            if constexpr (TRANSB) {
                const int row = idx >> 3, k4 = (idx & 7) * 4;
                rB[i] = *reinterpret_cast<const float4*>(Bp + (size_t)(n0 + row) * LDB_ + k0 + k4);
            } else {
                constexpr int R4 = BN / 4;
                const int row = idx / R4, n4 = (idx % R4) * 4;
                rB[i] = *reinterpret_cast<const float4*>(Bp + (size_t)(k0 + row) * LDB_ + n0 + n4);
            }
        }
    };
    auto stage = [&](int st) {
        __nv_bfloat16* ah = AsH + st*A_STG;
        __nv_bfloat16* al = AsL + st*A_STG;
        #pragma unroll
        for (int i = 0; i < 4; i++) {
            const int idx = t + i*256;
            const int row = idx >> 3, k4 = (idx & 7) * 4;
            uint2 hi, lo; split4(rA[i], hi, lo);
            *reinterpret_cast<uint2*>(ah + row*LDAS + k4) = hi;
            *reinterpret_cast<uint2*>(al + row*LDAS + k4) = lo;
        }
        __nv_bfloat16* bh = BsH + st*B_STG;
        __nv_bfloat16* bl = BsL + st*B_STG;
        #pragma unroll
        for (int i = 0; i < NB4; i++) {
            const int idx = t + i*256;
            uint2 hi, lo; split4(rB[i], hi, lo);
            if constexpr (TRANSB) {
                const int row = idx >> 3, k4 = (idx & 7) * 4;
                *reinterpret_cast<uint2*>(bh + row*LDBS + k4) = hi;
                *reinterpret_cast<uint2*>(bl + row*LDBS + k4) = lo;
            } else {
                constexpr int R4 = BN / 4;
                const int row = idx / R4, n4 = (idx % R4) * 4;
                *reinterpret_cast<uint2*>(bh + row*LDBS + n4) = hi;
                *reinterpret_cast<uint2*>(bl + row*LDBS + n4) = lo;
            }
        }
    };

    FragC acc[2][FN];
    #pragma unroll
    for (int i = 0; i < 2; i++)
        #pragma unroll
        for (int j = 0; j < FN; j++) wmma::fill_fragment(acc[i][j], 0.f);

    fetchA(0); fetchB(0);
    stage(0);
    __syncthreads();

    for (int kt = 0; kt < KT; kt++) {
        const int st = kt & 1;
        if (kt + 1 < KT) { fetchA((kt+1)*BK); fetchB((kt+1)*BK); }

        const __nv_bfloat16* ah = AsH + st*A_STG;
        const __nv_bfloat16* al = AsL + st*A_STG;
        const __nv_bfloat16* bh = BsH + st*B_STG;
        const __nv_bfloat16* bl = BsL + st*B_STG;

        #pragma unroll
        for (int ks = 0; ks < 2; ks++) {
            FragA fah[2], fal[2];
            #pragma unroll
            for (int im = 0; im < 2; im++) {
                const int ro = (wm*32 + im*16)*LDAS + ks*16;
                wmma::load_matrix_sync(fah[im], ah + ro, LDAS);
                wmma::load_matrix_sync(fal[im], al + ro, LDAS);
            }
            if constexpr (TRANSB) {
                FragBC fbh[FN], fbl[FN];
                #pragma unroll
                for (int in_ = 0; in_ < FN; in_++) {
                    const int bo = (wn*WN + in_*16)*LDBS + ks*16;
                    wmma::load_matrix_sync(fbh[in_], bh + bo, LDBS);
                    wmma::load_matrix_sync(fbl[in_], bl + bo, LDBS);
                }
                #pragma unroll
                for (int im = 0; im < 2; im++)
                    #pragma unroll
                    for (int in_ = 0; in_ < FN; in_++) {
                        wmma::mma_sync(acc[im][in_], fah[im], fbh[in_], acc[im][in_]);
                        wmma::mma_sync(acc[im][in_], fal[im], fbh[in_], acc[im][in_]);
                        wmma::mma_sync(acc[im][in_], fah[im], fbl[in_], acc[im][in_]);
                    }
            } else {
                FragBR fbh[FN], fbl[FN];
                #pragma unroll
                for (int in_ = 0; in_ < FN; in_++) {
                    const int bo = (ks*16)*LDBS + wn*WN + in_*16;
                    wmma::load_matrix_sync(fbh[in_], bh + bo, LDBS);
                    wmma::load_matrix_sync(fbl[in_], bl + bo, LDBS);
                }
                #pragma unroll
                for (int im = 0; im < 2; im++)
                    #pragma unroll
                    for (int in_ = 0; in_ < FN; in_++) {
                        wmma::mma_sync(acc[im][in_], fah[im], fbh[in_], acc[im][in_]);
                        wmma::mma_sync(acc[im][in_], fal[im], fbh[in_], acc[im][in_]);
                        wmma::mma_sync(acc[im][in_], fah[im], fbl[in_], acc[im][in_]);
                    }
            }
        }

        if (kt + 1 < KT) stage(st ^ 1);
        __syncthreads();
    }

    if constexpr (EPI == EPI_DOTS) {
        float* stg = reinterpret_cast<float*>(sm);     // 128 x 132 fp32
        #pragma unroll
        for (int im = 0; im < 2; im++)
            #pragma unroll
            for (int in_ = 0; in_ < FN; in_++)
                wmma::store_matrix_sync(&stg[(wm*32 + im*16)*132 + wn*WN + in_*16],
                                        acc[im][in_], 132, wmma::mem_row_major);
        __syncthreads();
        const int r = t >> 1, c0 = (t & 1) * 64;
        float ssum = 0.f;
        float* grow = g_s + ((size_t)z << 20) + (size_t)(m0 + r)*NSEQ + n0 + c0;
        #pragma unroll
        for (int u = 0; u < 64; u += 4) {
            float4 v4 = *reinterpret_cast<float4*>(&stg[r*132 + c0 + u]);
            v4.x = __expf(v4.x*0.125f); v4.y = __expf(v4.y*0.125f);
            v4.z = __expf(v4.z*0.125f); v4.w = __expf(v4.w*0.125f);
            ssum += v4.x + v4.y + v4.z + v4.w;
            *reinterpret_cast<float4*>(grow + u) = v4;
        }
        ssum += __shfl_xor_sync(0xffffffffu, ssum, 1);
        if ((t & 1) == 0)
            g_part[((size_t)(z*8 + blockIdx.x) << 10) + m0 + r] = ssum;
        return;
    }

    if constexpr (EPI == EPI_QKV) {
        if (n0 < 1024) {
            #pragma unroll
            for (int im = 0; im < 2; im++) {
                const int row0 = m0 + wm*32 + im*16;
                #pragma unroll
                for (int in_ = 0; in_ < FN; in_++) {
                    const int c0 = n0 + wn*WN + in_*16;
                    const int part = c0 >> 9, h = (c0 & 511) >> 6, d = c0 & 63;
                    const int b = row0 >> 10, nr = row0 & 1023;
                    float* base = (part == 0) ? g_q : g_k;
                    wmma::store_matrix_sync(base + (((size_t)(b*NH + h))*NSEQ + nr)*HD + d,
                                            acc[im][in_], HD, wmma::mem_row_major);
                }
            }
        } else {
            // v: stage fp32 -> split to fp16 hi/lo planes
            float* stg = reinterpret_cast<float*>(sm);   // 128 x 136
            #pragma unroll
            for (int im = 0; im < 2; im++)
                #pragma unroll
                for (int in_ = 0; in_ < FN; in_++)
                    wmma::store_matrix_sync(&stg[(wm*32 + im*16)*136 + wn*WN + in_*16],
                                            acc[im][in_], 136, wmma::mem_row_major);
            __syncthreads();
            #pragma unroll
            for (int u = 0; u < 16; u++) {
                const int idx = t + u*256;
                const int lr = idx >> 5, lc4 = (idx & 31) * 4;
                const float4 v4 = *reinterpret_cast<float4*>(&stg[lr*136 + lc4]);
                const int col = (n0 - 1024) + lc4;
                const int h = col >> 6, d = col & 63;
                const int m = m0 + lr;
                const int b = m >> 10, nr = m & 1023;
                uint2 hi, lo; split4h(v4, hi, lo);
                const size_t o = (((size_t)(b*NH + h)) << 16) + nr*HD + d;
                *reinterpret_cast<uint2*>(v_hi + o) = hi;
                *reinterpret_cast<uint2*>(v_lo + o) = lo;
            }
        }
        return;
    }

    // EPI_OUT
    #pragma unroll
    for (int im = 0; im < 2; im++) {
        const int row0 = m0 + wm*32 + im*16;
        #pragma unroll
        for (int in_ = 0; in_ < FN; in_++) {
            const int c0 = n0 + wn*WN + in_*16;
            wmma::store_matrix_sync(Cout + (size_t)row0*CDIM + c0,
                                    acc[im][in_], CDIM, wmma::mem_row_major);
        }
    }
}

// ---------------------------------------------------------------------------
// Lean normalize + remix + LN: p = e/S (exp done in DOTS), remix, LN, -> fp16
// CTA per (b, i); warp w = head w. (r11-proven structure minus exp/max/sum.)
// ---------------------------------------------------------------------------
__global__ __launch_bounds__(256)
void norm_remix_ln(const float* __restrict__ W,
                   const float* __restrict__ gamma,
                   const float* __restrict__ beta)
{
    __shared__ float s[NH][NSEQ];
    __shared__ float w_s[64], gm[8], bt[8];

    const int t = threadIdx.x;
    const int bi = blockIdx.x;
    const int b = bi >> 10, i = bi & 1023;

    if (t < 64) w_s[t] = W[t];
    if (t >= 64 && t < 72) { gm[t-64] = gamma[t-64]; bt[t-64] = beta[t-64]; }

    const int wid = t >> 5, lid = t & 31;
    {
        float S = 0.f;
        const float* pp = g_part + (((size_t)(b*NH + wid)) << 13) + i;
        #pragma unroll
        for (int nt = 0; nt < 8; nt++) S += pp[nt << 10];
        const float inv = 1.f / S;
        const float* row = g_s + (((size_t)(b*NH + wid)) << 20) + (size_t)i*NSEQ;
        #pragma unroll
        for (int u = 0; u < 8; u++) {
            const int j = lid*4 + u*128;
            float4 e4 = *reinterpret_cast<const float4*>(row + j);
            s[wid][j+0] = e4.x*inv; s[wid][j+1] = e4.y*inv;
            s[wid][j+2] = e4.z*inv; s[wid][j+3] = e4.w*inv;
        }
    }
    __syncthreads();

    #pragma unroll
    for (int u = 0; u < 4; u++) {
        const int j = t + 256*u;
        float a[8], mix[8];
        #pragma unroll
        for (int h = 0; h < 8; h++) a[h] = s[h][j];
        float mean = 0.f;
        #pragma unroll
        for (int g = 0; g < 8; g++) {
            float acc = 0.f;
            #pragma unroll
            for (int h = 0; h < 8; h++) acc += a[h] * w_s[h*8 + g];
            mix[g] = acc; mean += acc;
        }
        mean *= 0.125f;
        float var = 0.f;
        #pragma unroll
        for (int g = 0; g < 8; g++) { const float d = mix[g] - mean; var += d*d; }
        var *= 0.125f;
        const float rstd = rsqrtf(var + 1e-5f);
        #pragma unroll
        for (int g = 0; g < 8; g++) {
            const float o = (mix[g] - mean) * rstd * gm[g] + bt[g];
            g_a[(((size_t)(b*NH + g)) << 20) + ((size_t)i << 10) + j] = __float2half(o);
        }
    }
}

// ---------------------------------------------------------------------------
// PV GEMM, 2-term fp16: D = A*Vh + A*Vl.  A = attn fp16 (no split needed).
// BM=128, BN=64, BK=32; double-buffered; direct store to g_oh.
// ---------------------------------------------------------------------------
__global__ __launch_bounds__(256, 2)
void pv_gemm()
{
    constexpr int BK = 32, KT = NSEQ / BK;
    __shared__ __align__(128) __half Ast[2][128*40];
    __shared__ __align__(128) __half Bh[2][32*72];
    __shared__ __align__(128) __half Bl[2][32*72];

    const int t   = threadIdx.x;
    const int wid = t >> 5;
    const int wm  = wid & 3, wn = wid >> 2;
    const int m0  = blockIdx.y * 128;
    const int z   = blockIdx.z;

    const __half* Ap  = g_a + ((size_t)z << 20);
    const __half* vhg = v_hi + ((size_t)z << 16);
    const __half* vlg = v_lo + ((size_t)z << 16);

    uint4 rA[2], rBh, rBl;
    auto fetchA = [&](int k0) {
        #pragma unroll
        for (int i = 0; i < 2; i++) {
            const int idx = t + i*256;               // 512 uint4 = 128 rows x 4
            const int row = idx >> 2, c8 = (idx & 3) * 8;
            rA[i] = *reinterpret_cast<const uint4*>(Ap + (size_t)(m0 + row)*NSEQ + k0 + c8);
        }
    };
    auto fetchB = [&](int k0) {
        const int row = t >> 3, d8 = (t & 7) * 8;    // 256 uint4 = 32 rows x 8
        rBh = *reinterpret_cast<const uint4*>(vhg + (size_t)(k0 + row)*HD + d8);
        rBl = *reinterpret_cast<const uint4*>(vlg + (size_t)(k0 + row)*HD + d8);
    };
    auto stage = [&](int st) {
        #pragma unroll
        for (int i = 0; i < 2; i++) {
            const int idx = t + i*256;
            const int row = idx >> 2, c8 = (idx & 3) * 8;
            *reinterpret_cast<uint4*>(&Ast[st][row*40 + c8]) = rA[i];
        }
        const int row = t >> 3, d8 = (t & 7) * 8;
        *reinterpret_cast<uint4*>(&Bh[st][row*72 + d8]) = rBh;
        *reinterpret_cast<uint4*>(&Bl[st][row*72 + d8]) = rBl;
    };

    FragC acc[2][2];
    #pragma unroll
    for (int i = 0; i < 2; i++)
        #pragma unroll
        for (int j = 0; j < 2; j++) wmma::fill_fragment(acc[i][j], 0.f);

    fetchA(0); fetchB(0);
    stage(0);
    __syncthreads();

    for (int kt = 0; kt < KT; kt++) {
        const int st = kt & 1;
        if (kt + 1 < KT) { fetchA((kt+1)*BK); fetchB((kt+1)*BK); }

        #pragma unroll
        for (int ks = 0; ks < 2; ks++) {
            HFragA fa[2];
            #pragma unroll
            for (int im = 0; im < 2; im++)
                wmma::load_matrix_sync(fa[im], &Ast[st][(wm*32 + im*16)*40 + ks*16], 40);
            HFragB fbh[2], fbl[2];
            #pragma unroll
            for (int in_ = 0; in_ < 2; in_++) {
                wmma::load_matrix_sync(fbh[in_], &Bh[st][(ks*16)*72 + wn*32 + in_*16], 72);
                wmma::load_matrix_sync(fbl[in_], &Bl[st][(ks*16)*72 + wn*32 + in_*16], 72);
            }
            #pragma unroll
            for (int im = 0; im < 2; im++)
                #pragma unroll
                for (int in_ = 0; in_ < 2; in_++) {
                    wmma::mma_sync(acc[im][in_], fa[im], fbh[in_], acc[im][in_]);
                    wmma::mma_sync(acc[im][in_], fa[im], fbl[in_], acc[im][in_]);
                }
        }

        if (kt + 1 < KT) stage(st ^ 1);
        __syncthreads();
    }

    const int b = z >> 3, h = z & 7;
    #pragma unroll
    for (int im = 0; im < 2; im++) {
        const int row0 = m0 + wm*32 + im*16;
        #pragma unroll
        for (int in_ = 0; in_ < 2; in_++) {
            const int c0 = wn*32 + in_*16;
            wmma::store_matrix_sync(g_oh + ((size_t)(b*NSEQ + row0))*CDIM + h*HD + c0,
                                    acc[im][in_], CDIM, wmma::mem_row_major);
        }
    }
}

__global__ void bias_add_k(float* __restrict__ out, const float* __restrict__ bias)
{
    const int i = blockIdx.x * blockDim.x + threadIdx.x;
    out[i] += bias[i & (CDIM-1)];
}

// ---------------------------------------------------------------------------
extern "C" void kernel_launch(void* const* d_in, const int* in_sizes, int n_in,
                              void* d_out, int out_size)
{
    const float* x      = (const float*)d_in[0];
    const float* w_qkv  = (const float*)d_in[1];
    const float* reattn = (const float*)d_in[2];
    const float* gamma  = (const float*)d_in[3];
    const float* beta   = (const float*)d_in[4];
    const float* w_out  = (const float*)d_in[5];
    const float* b_out  = (const float*)d_in[6];
    float* out = (float*)d_out;

    constexpr int SM_QKV  = 2*(4*128*40 + 4*32*136);   // 75776 (>= 69632 V staging)
    constexpr int SM_DOTS = 2*(4*128*40 + 4*128*40);   // 81920 (>= 67584 staging)
    constexpr int SM_OUT  = SM_QKV;

    cudaFuncSetAttribute(tgemm<EPI_QKV, 512, 512, 1536, false, 128>, cudaFuncAttributeMaxDynamicSharedMemorySize, SM_QKV);
    cudaFuncSetAttribute(tgemm<EPI_DOTS, 64, 64, 64, true, 128>,     cudaFuncAttributeMaxDynamicSharedMemorySize, SM_DOTS);
    cudaFuncSetAttribute(tgemm<EPI_OUT, 512, 512, 512, false, 128>,  cudaFuncAttributeMaxDynamicSharedMemorySize, SM_OUT);

    // 1) qkv = x @ w_qkv -> q/k fp32, v fp16 hi/lo planes
    tgemm<EPI_QKV, 512, 512, 1536, false, 128>
        <<<dim3(12, 64, 1), 256, SM_QKV>>>(x, w_qkv, nullptr);
    // 2) e = exp(scale * q@k^T) -> g_s, partials -> g_part
    tgemm<EPI_DOTS, 64, 64, 64, true, 128>
        <<<dim3(8, 8, 64), 256, SM_DOTS>>>(nullptr, nullptr, nullptr);
    // 3) normalize + remix + LN -> attn fp16
    norm_remix_ln<<<NB*NSEQ, 256>>>(reattn, gamma, beta);
    // 4) out_h = attn @ v (2-term fp16)
    pv_gemm<<<dim3(1, 8, 64), 256>>>();
    // 5) out = g_oh @ w_out ; then + b_out
    tgemm<EPI_OUT, 512, 512, 512, false, 128>
        <<<dim3(4, 64, 1), 256, SM_OUT>>>(nullptr, w_out, out);
    bias_add_k<<<(8192*512)/256, 256>>>(out, b_out);
}

// round 15
// speedup vs baseline: 1.4570x; 1.0426x over previous
#include <cuda_runtime.h>
#include <cuda_bf16.h>
#include <cuda_fp16.h>
#include <mma.h>
#include <cstdint>

using namespace nvcuda;

#define NB 8
#define NSEQ 1024
#define NH 8
#define HD 64
#define CDIM 512

__device__ float g_q[NB*NH*NSEQ*HD];
__device__ float g_k[NB*NH*NSEQ*HD];
__device__ __half v_hi[NB*NH*NSEQ*HD];
__device__ __half v_lo[NB*NH*NSEQ*HD];
__device__ __half g_s[(size_t)NB*NH*NSEQ*NSEQ]; // 128 MB: exp(scale*dots) fp16
__device__ float g_part[NB*NH*8*NSEQ];          // per-(z, n-tile) row sums of exp
__device__ __half g_a[(size_t)NB*NH*NSEQ*NSEQ]; // 128 MB: final attn (fp16)
__device__ float g_oh[NB*NSEQ*CDIM];

#define EPI_QKV  0
#define EPI_DOTS 1
#define EPI_OUT  3

using FragA  = wmma::fragment<wmma::matrix_a, 16, 16, 16, __nv_bfloat16, wmma::row_major>;
using FragBR = wmma::fragment<wmma::matrix_b, 16, 16, 16, __nv_bfloat16, wmma::row_major>;
using FragBC = wmma::fragment<wmma::matrix_b, 16, 16, 16, __nv_bfloat16, wmma::col_major>;
using FragC  = wmma::fragment<wmma::accumulator, 16, 16, 16, float>;
using HFragA = wmma::fragment<wmma::matrix_a, 16, 16, 16, __half, wmma::row_major>;
using HFragB = wmma::fragment<wmma::matrix_b, 16, 16, 16, __half, wmma::row_major>;

__device__ __forceinline__ void split4(const float4 v, uint2& hi, uint2& lo) {
    __nv_bfloat16 hx = __float2bfloat16(v.x), hy = __float2bfloat16(v.y);
    __nv_bfloat16 hz = __float2bfloat16(v.z), hw = __float2bfloat16(v.w);
    __nv_bfloat16 lx = __float2bfloat16(v.x - __bfloat162float(hx));
    __nv_bfloat16 ly = __float2bfloat16(v.y - __bfloat162float(hy));
    __nv_bfloat16 lz = __float2bfloat16(v.z - __bfloat162float(hz));
    __nv_bfloat16 lw = __float2bfloat16(v.w - __bfloat162float(hw));
    __nv_bfloat162 h0{hx, hy}, h1{hz, hw}, l0{lx, ly}, l1{lz, lw};
    hi.x = *reinterpret_cast<unsigned int*>(&h0); hi.y = *reinterpret_cast<unsigned int*>(&h1);
    lo.x = *reinterpret_cast<unsigned int*>(&l0); lo.y = *reinterpret_cast<unsigned int*>(&l1);
}

__device__ __forceinline__ void split4h(const float4 v, uint2& hi, uint2& lo) {
    __half hx = __float2half(v.x), hy = __float2half(v.y);
    __half hz = __float2half(v.z), hw = __float2half(v.w);
    __half lx = __float2half(v.x - __half2float(hx));
    __half ly = __float2half(v.y - __half2float(hy));
    __half lz = __float2half(v.z - __half2float(hz));
    __half lw = __float2half(v.w - __half2float(hw));
    __half2 h0{hx, hy}, h1{hz, hw}, l0{lx, ly}, l1{lz, lw};
    hi.x = *reinterpret_cast<unsigned int*>(&h0); hi.y = *reinterpret_cast<unsigned int*>(&h1);
    lo.x = *reinterpret_cast<unsigned int*>(&l0); lo.y = *reinterpret_cast<unsigned int*>(&l1);
}

// ---------------------------------------------------------------------------
// 3-term bf16-split wmma GEMM (proven r11-r14 mainloop).
//  EPI_QKV: q/k direct stores; v -> fp16 hi/lo planes via smem stage.
//  EPI_DOTS: exp(0.125*dot) -> g_s (fp16) + row partial sums.
//  EPI_OUT: direct store.
// ---------------------------------------------------------------------------
template<int EPI, int KD, int LDA_, int LDB_, bool TRANSB, int BN>
__global__ __launch_bounds__(256, 2)
void tgemm(const float* __restrict__ Ain, const float* __restrict__ Bin,
           float* __restrict__ Cout)
{
    constexpr int BM = 128, BK = 32, KT = KD / BK;
    constexpr int FN = BN / 32;
    constexpr int WN = BN / 2;
    constexpr int LDAS = 40;
    constexpr int A_STG = BM * LDAS;
    constexpr int LDBS = TRANSB ? 40 : (BN + 8);
    constexpr int B_STG = TRANSB ? (BN * 40) : (BK * (BN + 8));
    constexpr int NB4 = BN / 32;

    extern __shared__ __align__(128) __nv_bfloat16 sm[];
    __nv_bfloat16* AsH = sm;
    __nv_bfloat16* AsL = sm + 2*A_STG;
    __nv_bfloat16* BsH = sm + 4*A_STG;
    __nv_bfloat16* BsL = sm + 4*A_STG + 2*B_STG;

    const int t   = threadIdx.x;
    const int wid = t >> 5;
    const int wm  = wid & 3, wn = wid >> 2;
    const int m0  = blockIdx.y * BM;
    const int n0  = blockIdx.x * BN;
    const int z   = blockIdx.z;

    const float* Ap;
    const float* Bp;
    if      constexpr (EPI == EPI_QKV)  { Ap = Ain;                     Bp = Bin; }
    else if constexpr (EPI == EPI_DOTS) { Ap = g_q + (size_t)z*NSEQ*HD; Bp = g_k + (size_t)z*NSEQ*HD; }
    else                                { Ap = g_oh;                    Bp = Bin; }

    float4 rA[4], rB[NB4];

    auto fetchA = [&](int k0) {
        #pragma unroll
        for (int i = 0; i < 4; i++) {
            const int idx = t + i*256;
            const int row = idx >> 3, k4 = (idx & 7) * 4;
            rA[i] = *reinterpret_cast<const float4*>(Ap + (size_t)(m0 + row) * LDA_ + k0 + k4);
        }
    };
    auto fetchB = [&](int k0) {
        #pragma unroll
        for (int i = 0; i < NB4; i++) {
            const int idx = t + i*256;
            if constexpr (TRANSB) {
                const int row = idx >> 3, k4 = (idx & 7) * 4;
                rB[i] = *reinterpret_cast<const float4*>(Bp + (size_t)(n0 + row) * LDB_ + k0 + k4);
            } else {
                constexpr int R4 = BN / 4;
                const int row = idx / R4, n4 = (idx % R4) * 4;
                rB[i] = *reinterpret_cast<const float4*>(Bp + (size_t)(k0 + row) * LDB_ + n0 + n4);
            }
        }
    };
    auto stage = [&](int st) {
        __nv_bfloat16* ah = AsH + st*A_STG;
        __nv_bfloat16* al = AsL + st*A_STG;
        #pragma unroll
        for (int i = 0; i < 4; i++) {
            const int idx = t + i*256;
            const int row = idx >> 3, k4 = (idx & 7) * 4;
            uint2 hi, lo; split4(rA[i], hi, lo);
            *reinterpret_cast<uint2*>(ah + row*LDAS + k4) = hi;
            *reinterpret_cast<uint2*>(al + row*LDAS + k4) = lo;
        }
        __nv_bfloat16* bh = BsH + st*B_STG;
        __nv_bfloat16* bl = BsL + st*B_STG;
        #pragma unroll
        for (int i = 0; i < NB4; i++) {
            const int idx = t + i*256;
            uint2 hi, lo; split4(rB[i], hi, lo);
            if constexpr (TRANSB) {
                const int row = idx >> 3, k4 = (idx & 7) * 4;
                *reinterpret_cast<uint2*>(bh + row*LDBS + k4) = hi;
                *reinterpret_cast<uint2*>(bl + row*LDBS + k4) = lo;
            } else {
                constexpr int R4 = BN / 4;
                const int row = idx / R4, n4 = (idx % R4) * 4;
                *reinterpret_cast<uint2*>(bh + row*LDBS + n4) = hi;
                *reinterpret_cast<uint2*>(bl + row*LDBS + n4) = lo;
            }
        }
    };

    FragC acc[2][FN];
    #pragma unroll
    for (int i = 0; i < 2; i++)
        #pragma unroll
        for (int j = 0; j < FN; j++) wmma::fill_fragment(acc[i][j], 0.f);

    fetchA(0); fetchB(0);
    stage(0);
    __syncthreads();

    for (int kt = 0; kt < KT; kt++) {
        const int st = kt & 1;
        if (kt + 1 < KT) { fetchA((kt+1)*BK); fetchB((kt+1)*BK); }

        const __nv_bfloat16* ah = AsH + st*A_STG;
        const __nv_bfloat16* al = AsL + st*A_STG;
        const __nv_bfloat16* bh = BsH + st*B_STG;
        const __nv_bfloat16* bl = BsL + st*B_STG;

        #pragma unroll
        for (int ks = 0; ks < 2; ks++) {
            FragA fah[2], fal[2];
            #pragma unroll
            for (int im = 0; im < 2; im++) {
                const int ro = (wm*32 + im*16)*LDAS + ks*16;
                wmma::load_matrix_sync(fah[im], ah + ro, LDAS);
                wmma::load_matrix_sync(fal[im], al + ro, LDAS);
            }
            if constexpr (TRANSB) {
                FragBC fbh[FN], fbl[FN];
                #pragma unroll
                for (int in_ = 0; in_ < FN; in_++) {
                    const int bo = (wn*WN + in_*16)*LDBS + ks*16;
                    wmma::load_matrix_sync(fbh[in_], bh + bo, LDBS);
                    wmma::load_matrix_sync(fbl[in_], bl + bo, LDBS);
                }
                #pragma unroll
                for (int im = 0; im < 2; im++)
                    #pragma unroll
                    for (int in_ = 0; in_ < FN; in_++) {
                        wmma::mma_sync(acc[im][in_], fah[im], fbh[in_], acc[im][in_]);
                        wmma::mma_sync(acc[im][in_], fal[im], fbh[in_], acc[im][in_]);
                        wmma::mma_sync(acc[im][in_], fah[im], fbl[in_], acc[im][in_]);
                    }
            } else {
                FragBR fbh[FN], fbl[FN];
                #pragma unroll
                for (int in_ = 0; in_ < FN; in_++) {
                    const int bo = (ks*16)*LDBS + wn*WN + in_*16;
                    wmma::load_matrix_sync(fbh[in_], bh + bo, LDBS);
                    wmma::load_matrix_sync(fbl[in_], bl + bo, LDBS);
                }
                #pragma unroll
                for (int im = 0; im < 2; im++)
                    #pragma unroll
                    for (int in_ = 0; in_ < FN; in_++) {
                        wmma::mma_sync(acc[im][in_], fah[im], fbh[in_], acc[im][in_]);
                        wmma::mma_sync(acc[im][in_], fal[im], fbh[in_], acc[im][in_]);
                        wmma::mma_sync(acc[im][in_], fah[im], fbl[in_], acc[im][in_]);
                    }
            }
        }

        if (kt + 1 < KT) stage(st ^ 1);
        __syncthreads();
    }

    if constexpr (EPI == EPI_DOTS) {
        float* stg = reinterpret_cast<float*>(sm);     // 128 x 132 fp32
        #pragma unroll
        for (int im = 0; im < 2; im++)
            #pragma unroll
            for (int in_ = 0; in_ < FN; in_++)
                wmma::store_matrix_sync(&stg[(wm*32 + im*16)*132 + wn*WN + in_*16],
                                        acc[im][in_], 132, wmma::mem_row_major);
        __syncthreads();
        const int r = t >> 1, c0 = (t & 1) * 64;
        float ssum = 0.f;
        __half* grow = g_s + ((size_t)z << 20) + (size_t)(m0 + r)*NSEQ + n0 + c0;
        #pragma unroll
        for (int u = 0; u < 64; u += 8) {
            float4 v4 = *reinterpret_cast<float4*>(&stg[r*132 + c0 + u]);
            float4 w4 = *reinterpret_cast<float4*>(&stg[r*132 + c0 + u + 4]);
            v4.x = __expf(v4.x*0.125f); v4.y = __expf(v4.y*0.125f);
            v4.z = __expf(v4.z*0.125f); v4.w = __expf(v4.w*0.125f);
            w4.x = __expf(w4.x*0.125f); w4.y = __expf(w4.y*0.125f);
            w4.z = __expf(w4.z*0.125f); w4.w = __expf(w4.w*0.125f);
            ssum += v4.x + v4.y + v4.z + v4.w + w4.x + w4.y + w4.z + w4.w;
            __half2 p0 = __floats2half2_rn(v4.x, v4.y);
            __half2 p1 = __floats2half2_rn(v4.z, v4.w);
            __half2 p2 = __floats2half2_rn(w4.x, w4.y);
            __half2 p3 = __floats2half2_rn(w4.z, w4.w);
            uint4 pk;
            pk.x = *reinterpret_cast<unsigned int*>(&p0);
            pk.y = *reinterpret_cast<unsigned int*>(&p1);
            pk.z = *reinterpret_cast<unsigned int*>(&p2);
            pk.w = *reinterpret_cast<unsigned int*>(&p3);
            *reinterpret_cast<uint4*>(grow + u) = pk;
        }
        ssum += __shfl_xor_sync(0xffffffffu, ssum, 1);
        if ((t & 1) == 0)
            g_part[((size_t)(z*8 + blockIdx.x) << 10) + m0 + r] = ssum;
        return;
    }

    if constexpr (EPI == EPI_QKV) {
        if (n0 < 1024) {
            #pragma unroll
            for (int im = 0; im < 2; im++) {
                const int row0 = m0 + wm*32 + im*16;
                #pragma unroll
                for (int in_ = 0; in_ < FN; in_++) {
                    const int c0 = n0 + wn*WN + in_*16;
                    const int part = c0 >> 9, h = (c0 & 511) >> 6, d = c0 & 63;
                    const int b = row0 >> 10, nr = row0 & 1023;
                    float* base = (part == 0) ? g_q : g_k;
                    wmma::store_matrix_sync(base + (((size_t)(b*NH + h))*NSEQ + nr)*HD + d,
                                            acc[im][in_], HD, wmma::mem_row_major);
                }
            }
        } else {
            float* stg = reinterpret_cast<float*>(sm);   // 128 x 136
            #pragma unroll
            for (int im = 0; im < 2; im++)
                #pragma unroll
                for (int in_ = 0; in_ < FN; in_++)
                    wmma::store_matrix_sync(&stg[(wm*32 + im*16)*136 + wn*WN + in_*16],
                                            acc[im][in_], 136, wmma::mem_row_major);
            __syncthreads();
            #pragma unroll
            for (int u = 0; u < 16; u++) {
                const int idx = t + u*256;
                const int lr = idx >> 5, lc4 = (idx & 31) * 4;
                const float4 v4 = *reinterpret_cast<float4*>(&stg[lr*136 + lc4]);
                const int col = (n0 - 1024) + lc4;
                const int h = col >> 6, d = col & 63;
                const int m = m0 + lr;
                const int b = m >> 10, nr = m & 1023;
                uint2 hi, lo; split4h(v4, hi, lo);
                const size_t o = (((size_t)(b*NH + h)) << 16) + nr*HD + d;
                *reinterpret_cast<uint2*>(v_hi + o) = hi;
                *reinterpret_cast<uint2*>(v_lo + o) = lo;
            }
        }
        return;
    }

    // EPI_OUT
    #pragma unroll
    for (int im = 0; im < 2; im++) {
        const int row0 = m0 + wm*32 + im*16;
        #pragma unroll
        for (int in_ = 0; in_ < FN; in_++) {
            const int c0 = n0 + wn*WN + in_*16;
            wmma::store_matrix_sync(Cout + (size_t)row0*CDIM + c0,
                                    acc[im][in_], CDIM, wmma::mem_row_major);
        }
    }
}

// ---------------------------------------------------------------------------
// Lean normalize + remix + LN: p = e/S (exp done in DOTS), remix, LN.
// fp16 in, fp16 out; in-place smem buffer; per-warp coalesced output.
// ---------------------------------------------------------------------------
__global__ __launch_bounds__(256)
void norm_remix_ln(const float* __restrict__ W,
                   const float* __restrict__ gamma,
                   const float* __restrict__ beta)
{
    __shared__ float s[NH][NSEQ];
    __shared__ float w_s[64], gm[8], bt[8];

    const int t = threadIdx.x;
    const int bi = blockIdx.x;
    const int b = bi >> 10, i = bi & 1023;

    if (t < 64) w_s[t] = W[t];
    if (t >= 64 && t < 72) { gm[t-64] = gamma[t-64]; bt[t-64] = beta[t-64]; }

    const int wid = t >> 5, lid = t & 31;
    // load: warp wid handles head wid's row; fp16 e -> fp32 p
    {
        float S = 0.f;
        const float* pp = g_part + (((size_t)(b*NH + wid)) << 13) + i;
        #pragma unroll
        for (int nt = 0; nt < 8; nt++) S += pp[nt << 10];
        const float inv = 1.f / S;
        const __half* row = g_s + (((size_t)(b*NH + wid)) << 20) + ((size_t)i << 10);
        #pragma unroll
        for (int u = 0; u < 8; u++) {
            const int j = lid*4 + u*128;
            const uint2 h4 = *reinterpret_cast<const uint2*>(row + j);
            const __half2 e0 = *reinterpret_cast<const __half2*>(&h4.x);
            const __half2 e1 = *reinterpret_cast<const __half2*>(&h4.y);
            const float2 f0 = __half22float2(e0), f1 = __half22float2(e1);
            s[wid][j+0] = f0.x*inv; s[wid][j+1] = f0.y*inv;
            s[wid][j+2] = f1.x*inv; s[wid][j+3] = f1.y*inv;
        }
    }
    __syncthreads();

    // remix + LN, in place (each thread owns its j columns)
    #pragma unroll
    for (int u = 0; u < 4; u++) {
        const int j = t + 256*u;
        float a[8], mix[8];
        #pragma unroll
        for (int h = 0; h < 8; h++) a[h] = s[h][j];
        float mean = 0.f;
        #pragma unroll
        for (int g = 0; g < 8; g++) {
            float acc = 0.f;
            #pragma unroll
            for (int h = 0; h < 8; h++) acc += a[h] * w_s[h*8 + g];
            mix[g] = acc; mean += acc;
        }
        mean *= 0.125f;
        float var = 0.f;
        #pragma unroll
        for (int g = 0; g < 8; g++) { const float d = mix[g] - mean; var += d*d; }
        var *= 0.125f;
        const float rstd = rsqrtf(var + 1e-5f);
        #pragma unroll
        for (int g = 0; g < 8; g++)
            s[g][j] = (mix[g] - mean) * rstd * gm[g] + bt[g];
    }
    __syncthreads();

    // write: warp wid streams head wid's row, packed 8 halves/lane
    {
        __half* arow = g_a + (((size_t)(b*NH + wid)) << 20) + ((size_t)i << 10);
        #pragma unroll
        for (int u = 0; u < 4; u++) {
            const int j = lid*8 + u*256;
            const __half2 q0 = __floats2half2_rn(s[wid][j+0], s[wid][j+1]);
            const __half2 q1 = __floats2half2_rn(s[wid][j+2], s[wid][j+3]);
            const __half2 q2 = __floats2half2_rn(s[wid][j+4], s[wid][j+5]);
            const __half2 q3 = __floats2half2_rn(s[wid][j+6], s[wid][j+7]);
            uint4 pk;
            pk.x = *reinterpret_cast<const unsigned int*>(&q0);
            pk.y = *reinterpret_cast<const unsigned int*>(&q1);
            pk.z = *reinterpret_cast<const unsigned int*>(&q2);
            pk.w = *reinterpret_cast<const unsigned int*>(&q3);
            *reinterpret_cast<uint4*>(arow + j) = pk;
        }
    }
}

// ---------------------------------------------------------------------------
// PV GEMM, 2-term fp16 (r14 proven): D = A*Vh + A*Vl.
// ---------------------------------------------------------------------------
__global__ __launch_bounds__(256, 2)
void pv_gemm()
{
    constexpr int BK = 32, KT = NSEQ / BK;
    __shared__ __align__(128) __half Ast[2][128*40];
    __shared__ __align__(128) __half Bh[2][32*72];
    __shared__ __align__(128) __half Bl[2][32*72];

    const int t   = threadIdx.x;
    const int wid = t >> 5;
    const int wm  = wid & 3, wn = wid >> 2;
    const int m0  = blockIdx.y * 128;
    const int z   = blockIdx.z;

    const __half* Ap  = g_a + ((size_t)z << 20);
    const __half* vhg = v_hi + ((size_t)z << 16);
    const __half* vlg = v_lo + ((size_t)z << 16);

    uint4 rA[2], rBh, rBl;
    auto fetchA = [&](int k0) {
        #pragma unroll
        for (int i = 0; i < 2; i++) {
            const int idx = t + i*256;
            const int row = idx >> 2, c8 = (idx & 3) * 8;
            rA[i] = *reinterpret_cast<const uint4*>(Ap + (size_t)(m0 + row)*NSEQ + k0 + c8);
        }
    };
    auto fetchB = [&](int k0) {
        const int row = t >> 3, d8 = (t & 7) * 8;
        rBh = *reinterpret_cast<const uint4*>(vhg + (size_t)(k0 + row)*HD + d8);
        rBl = *reinterpret_cast<const uint4*>(vlg + (size_t)(k0 + row)*HD + d8);
    };
    auto stage = [&](int st) {
        #pragma unroll
        for (int i = 0; i < 2; i++) {
            const int idx = t + i*256;
            const int row = idx >> 2, c8 = (idx & 3) * 8;
            *reinterpret_cast<uint4*>(&Ast[st][row*40 + c8]) = rA[i];
        }
        const int row = t >> 3, d8 = (t & 7) * 8;
        *reinterpret_cast<uint4*>(&Bh[st][row*72 + d8]) = rBh;
        *reinterpret_cast<uint4*>(&Bl[st][row*72 + d8]) = rBl;
    };

    FragC acc[2][2];
    #pragma unroll
    for (int i = 0; i < 2; i++)
        #pragma unroll
        for (int j = 0; j < 2; j++) wmma::fill_fragment(acc[i][j], 0.f);

    fetchA(0); fetchB(0);
    stage(0);
    __syncthreads();

    for (int kt = 0; kt < KT; kt++) {
        const int st = kt & 1;
        if (kt + 1 < KT) { fetchA((kt+1)*BK); fetchB((kt+1)*BK); }

        #pragma unroll
        for (int ks = 0; ks < 2; ks++) {
            HFragA fa[2];
            #pragma unroll
            for (int im = 0; im < 2; im++)
                wmma::load_matrix_sync(fa[im], &Ast[st][(wm*32 + im*16)*40 + ks*16], 40);
            HFragB fbh[2], fbl[2];
            #pragma unroll
            for (int in_ = 0; in_ < 2; in_++) {
                wmma::load_matrix_sync(fbh[in_], &Bh[st][(ks*16)*72 + wn*32 + in_*16], 72);
                wmma::load_matrix_sync(fbl[in_], &Bl[st][(ks*16)*72 + wn*32 + in_*16], 72);
            }
            #pragma unroll
            for (int im = 0; im < 2; im++)
                #pragma unroll
                for (int in_ = 0; in_ < 2; in_++) {
                    wmma::mma_sync(acc[im][in_], fa[im], fbh[in_], acc[im][in_]);
                    wmma::mma_sync(acc[im][in_], fa[im], fbl[in_], acc[im][in_]);
                }
        }

        if (kt + 1 < KT) stage(st ^ 1);
        __syncthreads();
    }

    const int b = z >> 3, h = z & 7;
    #pragma unroll
    for (int im = 0; im < 2; im++) {
        const int row0 = m0 + wm*32 + im*16;
        #pragma unroll
        for (int in_ = 0; in_ < 2; in_++) {
            const int c0 = wn*32 + in_*16;
            wmma::store_matrix_sync(g_oh + ((size_t)(b*NSEQ + row0))*CDIM + h*HD + c0,
                                    acc[im][in_], CDIM, wmma::mem_row_major);
        }
    }
}

__global__ void bias_add_k(float* __restrict__ out, const float* __restrict__ bias)
{
    const int i = blockIdx.x * blockDim.x + threadIdx.x;
    out[i] += bias[i & (CDIM-1)];
}

// ---------------------------------------------------------------------------
extern "C" void kernel_launch(void* const* d_in, const int* in_sizes, int n_in,
                              void* d_out, int out_size)
{
    const float* x      = (const float*)d_in[0];
    const float* w_qkv  = (const float*)d_in[1];
    const float* reattn = (const float*)d_in[2];
    const float* gamma  = (const float*)d_in[3];
    const float* beta   = (const float*)d_in[4];
    const float* w_out  = (const float*)d_in[5];
    const float* b_out  = (const float*)d_in[6];
    float* out = (float*)d_out;

    constexpr int SM_QKV   = 2*(4*128*40 + 4*32*136);   // 75776 (>= 69632 V staging)
    constexpr int SM_DOTS  = 2*(4*128*40 + 4*128*40);   // 81920 (>= 67584 staging)
    constexpr int SM_OUT64 = 2*(4*128*40 + 4*32*72);    // 59392

    cudaFuncSetAttribute(tgemm<EPI_QKV, 512, 512, 1536, false, 128>, cudaFuncAttributeMaxDynamicSharedMemorySize, SM_QKV);
    cudaFuncSetAttribute(tgemm<EPI_DOTS, 64, 64, 64, true, 128>,     cudaFuncAttributeMaxDynamicSharedMemorySize, SM_DOTS);
    cudaFuncSetAttribute(tgemm<EPI_OUT, 512, 512, 512, false, 64>,   cudaFuncAttributeMaxDynamicSharedMemorySize, SM_OUT64);

    // 1) qkv = x @ w_qkv -> q/k fp32, v fp16 hi/lo planes
    tgemm<EPI_QKV, 512, 512, 1536, false, 128>
        <<<dim3(12, 64, 1), 256, SM_QKV>>>(x, w_qkv, nullptr);
    // 2) e = exp(scale * q@k^T) -> g_s (fp16), partials -> g_part
    tgemm<EPI_DOTS, 64, 64, 64, true, 128>
        <<<dim3(8, 8, 64), 256, SM_DOTS>>>(nullptr, nullptr, nullptr);
    // 3) normalize + remix + LN -> attn fp16
    norm_remix_ln<<<NB*NSEQ, 256>>>(reattn, gamma, beta);
    // 4) out_h = attn @ v (2-term fp16)
    pv_gemm<<<dim3(1, 8, 64), 256>>>();
    // 5) out = g_oh @ w_out (BN=64 for occupancy) ; then + b_out
    tgemm<EPI_OUT, 512, 512, 512, false, 64>
        <<<dim3(8, 64, 1), 256, SM_OUT64>>>(nullptr, w_out, out);
    bias_add_k<<<(8192*512)/256, 256>>>(out, b_out);
}

// round 17
// speedup vs baseline: 1.8974x; 1.3022x over previous
#include <cuda_runtime.h>
#include <cuda_bf16.h>
#include <cuda_fp16.h>
#include <mma.h>
#include <cstdint>

using namespace nvcuda;

#define NB 8
#define NSEQ 1024
#define NH 8
#define HD 64
#define CDIM 512

__device__ __half q_hi[NB*NH*NSEQ*HD], q_lo[NB*NH*NSEQ*HD];
__device__ __half k_h [NB*NH*NSEQ*HD];
__device__ __half v_hi[NB*NH*NSEQ*HD], v_lo[NB*NH*NSEQ*HD];
__device__ __half g_s[(size_t)NB*NH*NSEQ*NSEQ]; // 128 MB: exp(scale*dots) fp16
__device__ float  g_part[NB*NH*8*NSEQ];
__device__ __half g_a[(size_t)NB*NH*NSEQ*NSEQ]; // 128 MB: final attn fp16
__device__ float  g_oh[NB*NSEQ*CDIM];

using FragA   = wmma::fragment<wmma::matrix_a, 16, 16, 16, __nv_bfloat16, wmma::row_major>;
using FragBR  = wmma::fragment<wmma::matrix_b, 16, 16, 16, __nv_bfloat16, wmma::row_major>;
using FragC   = wmma::fragment<wmma::accumulator, 16, 16, 16, float>;
using HFragA  = wmma::fragment<wmma::matrix_a, 16, 16, 16, __half, wmma::row_major>;
using HFragB  = wmma::fragment<wmma::matrix_b, 16, 16, 16, __half, wmma::row_major>;
using HFragBC = wmma::fragment<wmma::matrix_b, 16, 16, 16, __half, wmma::col_major>;

__device__ __forceinline__ void split4(const float4 v, uint2& hi, uint2& lo) {
    __nv_bfloat16 hx = __float2bfloat16(v.x), hy = __float2bfloat16(v.y);
    __nv_bfloat16 hz = __float2bfloat16(v.z), hw = __float2bfloat16(v.w);
    __nv_bfloat16 lx = __float2bfloat16(v.x - __bfloat162float(hx));
    __nv_bfloat16 ly = __float2bfloat16(v.y - __bfloat162float(hy));
    __nv_bfloat16 lz = __float2bfloat16(v.z - __bfloat162float(hz));
    __nv_bfloat16 lw = __float2bfloat16(v.w - __bfloat162float(hw));
    __nv_bfloat162 h0{hx, hy}, h1{hz, hw}, l0{lx, ly}, l1{lz, lw};
    hi.x = *reinterpret_cast<unsigned int*>(&h0); hi.y = *reinterpret_cast<unsigned int*>(&h1);
    lo.x = *reinterpret_cast<unsigned int*>(&l0); lo.y = *reinterpret_cast<unsigned int*>(&l1);
}
__device__ __forceinline__ void split4h(const float4 v, uint2& hi, uint2& lo) {
    __half hx = __float2half(v.x), hy = __float2half(v.y);
    __half hz = __float2half(v.z), hw = __float2half(v.w);
    __half lx = __float2half(v.x - __half2float(hx));
    __half ly = __float2half(v.y - __half2float(hy));
    __half lz = __float2half(v.z - __half2float(hz));
    __half lw = __float2half(v.w - __half2float(hw));
    __half2 h0{hx, hy}, h1{hz, hw}, l0{lx, ly}, l1{lz, lw};
    hi.x = *reinterpret_cast<unsigned int*>(&h0); hi.y = *reinterpret_cast<unsigned int*>(&h1);
    lo.x = *reinterpret_cast<unsigned int*>(&l0); lo.y = *reinterpret_cast<unsigned int*>(&l1);
}
__device__ __forceinline__ uint2 pack4h(const float4 v) {
    __half2 a = __floats2half2_rn(v.x, v.y);
    __half2 b = __floats2half2_rn(v.z, v.w);
    uint2 r;
    r.x = *reinterpret_cast<const unsigned int*>(&a);
    r.y = *reinterpret_cast<const unsigned int*>(&b);
    return r;
}

// ---------------------------------------------------------------------------
// QKV: 2-term fp16.  D = (Xh + Xl) @ Wq_single.  BM=128, BN=128, BK=32, KT=16.
// Epilogue: q -> fp16 hi/lo, k -> fp16 single, v -> fp16 hi/lo.
// ---------------------------------------------------------------------------
__global__ __launch_bounds__(256, 2)
void qkv_gemm(const float* __restrict__ X, const float* __restrict__ Wq)
{
    constexpr int KT = 16, LDAS = 40, LDBS = 136;
    constexpr int A_STG = 128*LDAS;
    constexpr int B_STG = 32*LDBS;
    extern __shared__ __align__(128) __half hsm[];
    __half* AsH = hsm;
    __half* AsL = hsm + 2*A_STG;
    __half* Bs  = hsm + 4*A_STG;

    const int t = threadIdx.x, wid = t >> 5;
    const int wm = wid & 3, wn = wid >> 2;
    const int m0 = blockIdx.y * 128;
    const int n0 = blockIdx.x * 128;

    float4 rA[4], rB[4];
    auto fetchA = [&](int k0) {
        #pragma unroll
        for (int i = 0; i < 4; i++) {
            const int idx = t + i*256;
            const int row = idx >> 3, k4 = (idx & 7) * 4;
            rA[i] = *reinterpret_cast<const float4*>(X + (size_t)(m0 + row)*512 + k0 + k4);
        }
    };
    auto fetchB = [&](int k0) {
        #pragma unroll
        for (int i = 0; i < 4; i++) {
            const int idx = t + i*256;
            const int row = idx >> 5, n4 = (idx & 31) * 4;
            rB[i] = *reinterpret_cast<const float4*>(Wq + (size_t)(k0 + row)*1536 + n0 + n4);
        }
    };
    auto stage = [&](int st) {
        __half* ah = AsH + st*A_STG;
        __half* al = AsL + st*A_STG;
        #pragma unroll
        for (int i = 0; i < 4; i++) {
            const int idx = t + i*256;
            const int row = idx >> 3, k4 = (idx & 7) * 4;
            uint2 hi, lo; split4h(rA[i], hi, lo);
            *reinterpret_cast<uint2*>(ah + row*LDAS + k4) = hi;
            *reinterpret_cast<uint2*>(al + row*LDAS + k4) = lo;
        }
        __half* b = Bs + st*B_STG;
        #pragma unroll
        for (int i = 0; i < 4; i++) {
            const int idx = t + i*256;
            const int row = idx >> 5, n4 = (idx & 31) * 4;
            *reinterpret_cast<uint2*>(b + row*LDBS + n4) = pack4h(rB[i]);
        }
    };

    FragC acc[2][4];
    #pragma unroll
    for (int i = 0; i < 2; i++)
        #pragma unroll
        for (int j = 0; j < 4; j++) wmma::fill_fragment(acc[i][j], 0.f);

    fetchA(0); fetchB(0);
    stage(0);
    __syncthreads();

    for (int kt = 0; kt < KT; kt++) {
        const int st = kt & 1;
        if (kt + 1 < KT) { fetchA((kt+1)*32); fetchB((kt+1)*32); }
        const __half* ah = AsH + st*A_STG;
        const __half* al = AsL + st*A_STG;
        const __half* b  = Bs  + st*B_STG;
        #pragma unroll
        for (int ks = 0; ks < 2; ks++) {
            HFragA fah[2], fal[2];
            #pragma unroll
            for (int im = 0; im < 2; im++) {
                const int ro = (wm*32 + im*16)*LDAS + ks*16;
                wmma::load_matrix_sync(fah[im], ah + ro, LDAS);
                wmma::load_matrix_sync(fal[im], al + ro, LDAS);
            }
            HFragB fb[4];
            #pragma unroll
            for (int fn = 0; fn < 4; fn++)
                wmma::load_matrix_sync(fb[fn], b + (ks*16)*LDBS + wn*64 + fn*16, LDBS);
            #pragma unroll
            for (int im = 0; im < 2; im++)
                #pragma unroll
                for (int fn = 0; fn < 4; fn++) {
                    wmma::mma_sync(acc[im][fn], fah[im], fb[fn], acc[im][fn]);
                    wmma::mma_sync(acc[im][fn], fal[im], fb[fn], acc[im][fn]);
                }
        }
        if (kt + 1 < KT) stage(st ^ 1);
        __syncthreads();
    }

    float* stg = reinterpret_cast<float*>(hsm);   // 128 x 132
    #pragma unroll
    for (int im = 0; im < 2; im++)
        #pragma unroll
        for (int fn = 0; fn < 4; fn++)
            wmma::store_matrix_sync(&stg[(wm*32 + im*16)*132 + wn*64 + fn*16],
                                    acc[im][fn], 132, wmma::mem_row_major);
    __syncthreads();
    #pragma unroll
    for (int u = 0; u < 16; u++) {
        const int idx = t + u*256;
        const int lr = idx >> 5, lc4 = (idx & 31) * 4;
        const float4 v4 = *reinterpret_cast<float4*>(&stg[lr*132 + lc4]);
        const int c = n0 + lc4;
        const int part = c >> 9, rem = c & 511;
        const int h = rem >> 6, d = rem & 63;
        const int m = m0 + lr;
        const int b = m >> 10, nr = m & 1023;
        const size_t o = (((size_t)(b*NH + h)) << 16) + nr*HD + d;
        uint2 hi, lo; split4h(v4, hi, lo);
        if (part == 0) {
            *reinterpret_cast<uint2*>(q_hi + o) = hi;
            *reinterpret_cast<uint2*>(q_lo + o) = lo;
        } else if (part == 1) {
            *reinterpret_cast<uint2*>(k_h + o) = hi;
        } else {
            *reinterpret_cast<uint2*>(v_hi + o) = hi;
            *reinterpret_cast<uint2*>(v_lo + o) = lo;
        }
    }
}

// ---------------------------------------------------------------------------
// DOTS: 2-term fp16.  e = exp(0.125 * (Qh+Ql) @ Kh^T) -> g_s + row partials.
// BM=128, BN=128, KD=64 (BK=32, KT=2).  B col-major.
// FIXED LOADERS: 2 uint4 per thread per plane (512 uint4 = full 128x32 tile).
// ---------------------------------------------------------------------------
__global__ __launch_bounds__(256, 2)
void dots_gemm()
{
    constexpr int KT = 2, LDAS = 40, LDBS = 40;
    constexpr int A_STG = 128*LDAS;
    constexpr int B_STG = 128*LDBS;
    extern __shared__ __align__(128) __half hsm[];
    __half* AsH = hsm;
    __half* AsL = hsm + 2*A_STG;
    __half* Bs  = hsm + 4*A_STG;

    const int t = threadIdx.x, wid = t >> 5;
    const int wm = wid & 3, wn = wid >> 2;
    const int m0 = blockIdx.y * 128;
    const int n0 = blockIdx.x * 128;
    const int z  = blockIdx.z;

    const __half* qh = q_hi + ((size_t)z << 16);
    const __half* ql = q_lo + ((size_t)z << 16);
    const __half* kh = k_h  + ((size_t)z << 16);

    // loader mapping: row = t>>1 (0..127), k16 = (t&1)*16; chunks at +0, +8
    const int lrow = t >> 1, lk16 = (t & 1) * 16;

    uint4 rAh[2], rAl[2], rBv[2];
    auto fetchA = [&](int k0) {
        const __half* pq = qh + (size_t)(m0 + lrow)*HD + k0 + lk16;
        const __half* pl = ql + (size_t)(m0 + lrow)*HD + k0 + lk16;
        rAh[0] = *reinterpret_cast<const uint4*>(pq);
        rAh[1] = *reinterpret_cast<const uint4*>(pq + 8);
        rAl[0] = *reinterpret_cast<const uint4*>(pl);
        rAl[1] = *reinterpret_cast<const uint4*>(pl + 8);
    };
    auto fetchB = [&](int k0) {
        const __half* pk = kh + (size_t)(n0 + lrow)*HD + k0 + lk16;
        rBv[0] = *reinterpret_cast<const uint4*>(pk);
        rBv[1] = *reinterpret_cast<const uint4*>(pk + 8);
    };
    auto stage = [&](int st) {
        __half* ah = AsH + st*A_STG + lrow*LDAS + lk16;
        __half* al = AsL + st*A_STG + lrow*LDAS + lk16;
        __half* bb = Bs  + st*B_STG + lrow*LDBS + lk16;
        *reinterpret_cast<uint4*>(ah)     = rAh[0];
        *reinterpret_cast<uint4*>(ah + 8) = rAh[1];
        *reinterpret_cast<uint4*>(al)     = rAl[0];
        *reinterpret_cast<uint4*>(al + 8) = rAl[1];
        *reinterpret_cast<uint4*>(bb)     = rBv[0];
        *reinterpret_cast<uint4*>(bb + 8) = rBv[1];
    };

    FragC acc[2][4];
    #pragma unroll
    for (int i = 0; i < 2; i++)
        #pragma unroll
        for (int j = 0; j < 4; j++) wmma::fill_fragment(acc[i][j], 0.f);

    fetchA(0); fetchB(0);
    stage(0);
    __syncthreads();

    for (int kt = 0; kt < KT; kt++) {
        const int st = kt & 1;
        if (kt + 1 < KT) { fetchA((kt+1)*32); fetchB((kt+1)*32); }
        const __half* ah = AsH + st*A_STG;
        const __half* al = AsL + st*A_STG;
        const __half* b  = Bs  + st*B_STG;
        #pragma unroll
        for (int ks = 0; ks < 2; ks++) {
            HFragA fah[2], fal[2];
            #pragma unroll
            for (int im = 0; im < 2; im++) {
                const int ro = (wm*32 + im*16)*LDAS + ks*16;
                wmma::load_matrix_sync(fah[im], ah + ro, LDAS);
                wmma::load_matrix_sync(fal[im], al + ro, LDAS);
            }
            HFragBC fb[4];
            #pragma unroll
            for (int fn = 0; fn < 4; fn++)
                wmma::load_matrix_sync(fb[fn], b + (wn*64 + fn*16)*LDBS + ks*16, LDBS);
            #pragma unroll
            for (int im = 0; im < 2; im++)
                #pragma unroll
                for (int fn = 0; fn < 4; fn++) {
                    wmma::mma_sync(acc[im][fn], fah[im], fb[fn], acc[im][fn]);
                    wmma::mma_sync(acc[im][fn], fal[im], fb[fn], acc[im][fn]);
                }
        }
        if (kt + 1 < KT) stage(st ^ 1);
        __syncthreads();
    }

    float* stg = reinterpret_cast<float*>(hsm);   // 128 x 132
    #pragma unroll
    for (int im = 0; im < 2; im++)
        #pragma unroll
        for (int fn = 0; fn < 4; fn++)
            wmma::store_matrix_sync(&stg[(wm*32 + im*16)*132 + wn*64 + fn*16],
                                    acc[im][fn], 132, wmma::mem_row_major);
    __syncthreads();
    const int r = t >> 1, c0 = (t & 1) * 64;
    float ssum = 0.f;
    __half* grow = g_s + ((size_t)z << 20) + (size_t)(m0 + r)*NSEQ + n0 + c0;
    #pragma unroll
    for (int u = 0; u < 64; u += 8) {
        float4 v4 = *reinterpret_cast<float4*>(&stg[r*132 + c0 + u]);
        float4 w4 = *reinterpret_cast<float4*>(&stg[r*132 + c0 + u + 4]);
        v4.x = __expf(v4.x*0.125f); v4.y = __expf(v4.y*0.125f);
        v4.z = __expf(v4.z*0.125f); v4.w = __expf(v4.w*0.125f);
        w4.x = __expf(w4.x*0.125f); w4.y = __expf(w4.y*0.125f);
        w4.z = __expf(w4.z*0.125f); w4.w = __expf(w4.w*0.125f);
        ssum += v4.x + v4.y + v4.z + v4.w + w4.x + w4.y + w4.z + w4.w;
        uint4 pk;
        const uint2 p01 = pack4h(v4), p23 = pack4h(w4);
        pk.x = p01.x; pk.y = p01.y; pk.z = p23.x; pk.w = p23.y;
        *reinterpret_cast<uint4*>(grow + u) = pk;
    }
    ssum += __shfl_xor_sync(0xffffffffu, ssum, 1);
    if ((t & 1) == 0)
        g_part[((size_t)(z*8 + blockIdx.x) << 10) + m0 + r] = ssum;
}

// ---------------------------------------------------------------------------
// norm + remix + LN (r15 proven, unchanged)
// ---------------------------------------------------------------------------
__global__ __launch_bounds__(256)
void norm_remix_ln(const float* __restrict__ W,
                   const float* __restrict__ gamma,
                   const float* __restrict__ beta)
{
    __shared__ float s[NH][NSEQ];
    __shared__ float w_s[64], gm[8], bt[8];

    const int t = threadIdx.x;
    const int bi = blockIdx.x;
    const int b = bi >> 10, i = bi & 1023;

    if (t < 64) w_s[t] = W[t];
    if (t >= 64 && t < 72) { gm[t-64] = gamma[t-64]; bt[t-64] = beta[t-64]; }

    const int wid = t >> 5, lid = t & 31;
    {
        float S = 0.f;
        const float* pp = g_part + (((size_t)(b*NH + wid)) << 13) + i;
        #pragma unroll
        for (int nt = 0; nt < 8; nt++) S += pp[nt << 10];
        const float inv = 1.f / S;
        const __half* row = g_s + (((size_t)(b*NH + wid)) << 20) + ((size_t)i << 10);
        #pragma unroll
        for (int u = 0; u < 8; u++) {
            const int j = lid*4 + u*128;
            const uint2 h4 = *reinterpret_cast<const uint2*>(row + j);
            const __half2 e0 = *reinterpret_cast<const __half2*>(&h4.x);
            const __half2 e1 = *reinterpret_cast<const __half2*>(&h4.y);
            const float2 f0 = __half22float2(e0), f1 = __half22float2(e1);
            s[wid][j+0] = f0.x*inv; s[wid][j+1] = f0.y*inv;
            s[wid][j+2] = f1.x*inv; s[wid][j+3] = f1.y*inv;
        }
    }
    __syncthreads();

    #pragma unroll
    for (int u = 0; u < 4; u++) {
        const int j = t + 256*u;
        float a[8], mix[8];
        #pragma unroll
        for (int h = 0; h < 8; h++) a[h] = s[h][j];
        float mean = 0.f;
        #pragma unroll
        for (int g = 0; g < 8; g++) {
            float acc = 0.f;
            #pragma unroll
            for (int h = 0; h < 8; h++) acc += a[h] * w_s[h*8 + g];
            mix[g] = acc; mean += acc;
        }
        mean *= 0.125f;
        float var = 0.f;
        #pragma unroll
        for (int g = 0; g < 8; g++) { const float d = mix[g] - mean; var += d*d; }
        var *= 0.125f;
        const float rstd = rsqrtf(var + 1e-5f);
        #pragma unroll
        for (int g = 0; g < 8; g++)
            s[g][j] = (mix[g] - mean) * rstd * gm[g] + bt[g];
    }
    __syncthreads();

    {
        __half* arow = g_a + (((size_t)(b*NH + wid)) << 20) + ((size_t)i << 10);
        #pragma unroll
        for (int u = 0; u < 4; u++) {
            const int j = lid*8 + u*256;
            const float4 f0 = make_float4(s[wid][j+0], s[wid][j+1], s[wid][j+2], s[wid][j+3]);
            const float4 f1 = make_float4(s[wid][j+4], s[wid][j+5], s[wid][j+6], s[wid][j+7]);
            uint4 pk;
            const uint2 a0 = pack4h(f0), a1 = pack4h(f1);
            pk.x = a0.x; pk.y = a0.y; pk.z = a1.x; pk.w = a1.y;
            *reinterpret_cast<uint4*>(arow + j) = pk;
        }
    }
}

// ---------------------------------------------------------------------------
// PV GEMM, 2-term fp16 (r14/r15 proven): D = A*Vh + A*Vl.
// ---------------------------------------------------------------------------
__global__ __launch_bounds__(256, 2)
void pv_gemm()
{
    constexpr int BK = 32, KT = NSEQ / BK;
    __shared__ __align__(128) __half Ast[2][128*40];
    __shared__ __align__(128) __half Bh[2][32*72];
    __shared__ __align__(128) __half Bl[2][32*72];

    const int t   = threadIdx.x;
    const int wid = t >> 5;
    const int wm  = wid & 3, wn = wid >> 2;
    const int m0  = blockIdx.y * 128;
    const int z   = blockIdx.z;

    const __half* Ap  = g_a + ((size_t)z << 20);
    const __half* vhg = v_hi + ((size_t)z << 16);
    const __half* vlg = v_lo + ((size_t)z << 16);

    uint4 rA[2], rBh, rBl;
    auto fetchA = [&](int k0) {
        #pragma unroll
        for (int i = 0; i < 2; i++) {
            const int idx = t + i*256;
            const int row = idx >> 2, c8 = (idx & 3) * 8;
            rA[i] = *reinterpret_cast<const uint4*>(Ap + (size_t)(m0 + row)*NSEQ + k0 + c8);
        }
    };
    auto fetchB = [&](int k0) {
        const int row = t >> 3, d8 = (t & 7) * 8;
        rBh = *reinterpret_cast<const uint4*>(vhg + (size_t)(k0 + row)*HD + d8);
        rBl = *reinterpret_cast<const uint4*>(vlg + (size_t)(k0 + row)*HD + d8);
    };
    auto stage = [&](int st) {
        #pragma unroll
        for (int i = 0; i < 2; i++) {
            const int idx = t + i*256;
            const int row = idx >> 2, c8 = (idx & 3) * 8;
            *reinterpret_cast<uint4*>(&Ast[st][row*40 + c8]) = rA[i];
        }
        const int row = t >> 3, d8 = (t & 7) * 8;
        *reinterpret_cast<uint4*>(&Bh[st][row*72 + d8]) = rBh;
        *reinterpret_cast<uint4*>(&Bl[st][row*72 + d8]) = rBl;
    };

    FragC acc[2][2];
    #pragma unroll
    for (int i = 0; i < 2; i++)
        #pragma unroll
        for (int j = 0; j < 2; j++) wmma::fill_fragment(acc[i][j], 0.f);

    fetchA(0); fetchB(0);
    stage(0);
    __syncthreads();

    for (int kt = 0; kt < KT; kt++) {
        const int st = kt & 1;
        if (kt + 1 < KT) { fetchA((kt+1)*BK); fetchB((kt+1)*BK); }

        #pragma unroll
        for (int ks = 0; ks < 2; ks++) {
            HFragA fa[2];
            #pragma unroll
            for (int im = 0; im < 2; im++)
                wmma::load_matrix_sync(fa[im], &Ast[st][(wm*32 + im*16)*40 + ks*16], 40);
            HFragB fbh[2], fbl[2];
            #pragma unroll
            for (int in_ = 0; in_ < 2; in_++) {
                wmma::load_matrix_sync(fbh[in_], &Bh[st][(ks*16)*72 + wn*32 + in_*16], 72);
                wmma::load_matrix_sync(fbl[in_], &Bl[st][(ks*16)*72 + wn*32 + in_*16], 72);
            }
            #pragma unroll
            for (int im = 0; im < 2; im++)
                #pragma unroll
                for (int in_ = 0; in_ < 2; in_++) {
                    wmma::mma_sync(acc[im][in_], fa[im], fbh[in_], acc[im][in_]);
                    wmma::mma_sync(acc[im][in_], fa[im], fbl[in_], acc[im][in_]);
                }
        }

        if (kt + 1 < KT) stage(st ^ 1);
        __syncthreads();
    }

    const int b = z >> 3, h = z & 7;
    #pragma unroll
    for (int im = 0; im < 2; im++) {
        const int row0 = m0 + wm*32 + im*16;
        #pragma unroll
        for (int in_ = 0; in_ < 2; in_++) {
            const int c0 = wn*32 + in_*16;
            wmma::store_matrix_sync(g_oh + ((size_t)(b*NSEQ + row0))*CDIM + h*HD + c0,
                                    acc[im][in_], CDIM, wmma::mem_row_major);
        }
    }
}

// ---------------------------------------------------------------------------
// OUT: bf16 3-term + fused bias via staged epilogue. BN=64.
// ---------------------------------------------------------------------------
__global__ __launch_bounds__(256, 2)
void out_gemm(const float* __restrict__ Wo, const float* __restrict__ bias,
              float* __restrict__ Cout)
{
    constexpr int KT = 16, LDAS = 40, LDBS = 72;
    constexpr int A_STG = 128*LDAS;
    constexpr int B_STG = 32*LDBS;
    extern __shared__ __align__(128) __nv_bfloat16 sm[];
    __nv_bfloat16* AsH = sm;
    __nv_bfloat16* AsL = sm + 2*A_STG;
    __nv_bfloat16* BsH = sm + 4*A_STG;
    __nv_bfloat16* BsL = sm + 4*A_STG + 2*B_STG;

    const int t = threadIdx.x, wid = t >> 5;
    const int wm = wid & 3, wn = wid >> 2;
    const int m0 = blockIdx.y * 128;
    const int n0 = blockIdx.x * 64;

    float4 rA[4], rB[2];
    auto fetchA = [&](int k0) {
        #pragma unroll
        for (int i = 0; i < 4; i++) {
            const int idx = t + i*256;
            const int row = idx >> 3, k4 = (idx & 7) * 4;
            rA[i] = *reinterpret_cast<const float4*>(g_oh + (size_t)(m0 + row)*512 + k0 + k4);
        }
    };
    auto fetchB = [&](int k0) {
        #pragma unroll
        for (int i = 0; i < 2; i++) {
            const int idx = t + i*256;
            const int row = idx >> 4, n4 = (idx & 15) * 4;
            rB[i] = *reinterpret_cast<const float4*>(Wo + (size_t)(k0 + row)*512 + n0 + n4);
        }
    };
    auto stage = [&](int st) {
        __nv_bfloat16* ah = AsH + st*A_STG;
        __nv_bfloat16* al = AsL + st*A_STG;
        #pragma unroll
        for (int i = 0; i < 4; i++) {
            const int idx = t + i*256;
            const int row = idx >> 3, k4 = (idx & 7) * 4;
            uint2 hi, lo; split4(rA[i], hi, lo);
            *reinterpret_cast<uint2*>(ah + row*LDAS + k4) = hi;
            *reinterpret_cast<uint2*>(al + row*LDAS + k4) = lo;
        }
        __nv_bfloat16* bh = BsH + st*B_STG;
        __nv_bfloat16* bl = BsL + st*B_STG;
        #pragma unroll
        for (int i = 0; i < 2; i++) {
            const int idx = t + i*256;
            const int row = idx >> 4, n4 = (idx & 15) * 4;
            uint2 hi, lo; split4(rB[i], hi, lo);
            *reinterpret_cast<uint2*>(bh + row*LDBS + n4) = hi;
            *reinterpret_cast<uint2*>(bl + row*LDBS + n4) = lo;
        }
    };

    FragC acc[2][2];
    #pragma unroll
    for (int i = 0; i < 2; i++)
        #pragma unroll
        for (int j = 0; j < 2; j++) wmma::fill_fragment(acc[i][j], 0.f);

    fetchA(0); fetchB(0);
    stage(0);
    __syncthreads();

    for (int kt = 0; kt < KT; kt++) {
        const int st = kt & 1;
        if (kt + 1 < KT) { fetchA((kt+1)*32); fetchB((kt+1)*32); }
        const __nv_bfloat16* ah = AsH + st*A_STG;
        const __nv_bfloat16* al = AsL + st*A_STG;
        const __nv_bfloat16* bh = BsH + st*B_STG;
        const __nv_bfloat16* bl = BsL + st*B_STG;
        #pragma unroll
        for (int ks = 0; ks < 2; ks++) {
            FragA fah[2], fal[2];
            #pragma unroll
            for (int im = 0; im < 2; im++) {
                const int ro = (wm*32 + im*16)*LDAS + ks*16;
                wmma::load_matrix_sync(fah[im], ah + ro, LDAS);
                wmma::load_matrix_sync(fal[im], al + ro, LDAS);
            }
            FragBR fbh[2], fbl[2];
            #pragma unroll
            for (int fn = 0; fn < 2; fn++) {
                const int bo = (ks*16)*LDBS + wn*32 + fn*16;
                wmma::load_matrix_sync(fbh[fn], bh + bo, LDBS);
                wmma::load_matrix_sync(fbl[fn], bl + bo, LDBS);
            }
            #pragma unroll
            for (int im = 0; im < 2; im++)
                #pragma unroll
                for (int fn = 0; fn < 2; fn++) {
                    wmma::mma_sync(acc[im][fn], fah[im], fbh[fn], acc[im][fn]);
                    wmma::mma_sync(acc[im][fn], fal[im], fbh[fn], acc[im][fn]);
                    wmma::mma_sync(acc[im][fn], fah[im], fbl[fn], acc[im][fn]);
                }
        }
        if (kt + 1 < KT) stage(st ^ 1);
        __syncthreads();
    }

    float* stg = reinterpret_cast<float*>(sm);    // 128 x 68
    #pragma unroll
    for (int im = 0; im < 2; im++)
        #pragma unroll
        for (int fn = 0; fn < 2; fn++)
            wmma::store_matrix_sync(&stg[(wm*32 + im*16)*68 + wn*32 + fn*16],
                                    acc[im][fn], 68, wmma::mem_row_major);
    __syncthreads();
    #pragma unroll
    for (int u = 0; u < 8; u++) {
        const int idx = t + u*256;
        const int lr = idx >> 4, lc4 = (idx & 15) * 4;
        float4 v4 = *reinterpret_cast<float4*>(&stg[lr*68 + lc4]);
        const float4 b4 = *reinterpret_cast<const float4*>(bias + n0 + lc4);
        v4.x += b4.x; v4.y += b4.y; v4.z += b4.z; v4.w += b4.w;
        *reinterpret_cast<float4*>(Cout + (size_t)(m0 + lr)*512 + n0 + lc4) = v4;
    }
}

// ---------------------------------------------------------------------------
extern "C" void kernel_launch(void* const* d_in, const int* in_sizes, int n_in,
                              void* d_out, int out_size)
{
    const float* x      = (const float*)d_in[0];
    const float* w_qkv  = (const float*)d_in[1];
    const float* reattn = (const float*)d_in[2];
    const float* gamma  = (const float*)d_in[3];
    const float* beta   = (const float*)d_in[4];
    const float* w_out  = (const float*)d_in[5];
    const float* b_out  = (const float*)d_in[6];
    float* out = (float*)d_out;

    constexpr int SM_QKV  = 128*132*4;                // 67584 (staging dominates)
    constexpr int SM_DOTS = 128*132*4;                // 67584
    constexpr int SM_OUT  = 2*(4*128*40 + 4*32*72);   // 59392

    cudaFuncSetAttribute(qkv_gemm,  cudaFuncAttributeMaxDynamicSharedMemorySize, SM_QKV);
    cudaFuncSetAttribute(dots_gemm, cudaFuncAttributeMaxDynamicSharedMemorySize, SM_DOTS);
    cudaFuncSetAttribute(out_gemm,  cudaFuncAttributeMaxDynamicSharedMemorySize, SM_OUT);

    // 1) qkv (2-term fp16) -> q hi/lo, k single, v hi/lo
    qkv_gemm<<<dim3(12, 64), 256, SM_QKV>>>(x, w_qkv);
    // 2) e = exp(scale * q@k^T) (2-term fp16) -> g_s fp16, partials
    dots_gemm<<<dim3(8, 8, 64), 256, SM_DOTS>>>();
    // 3) normalize + remix + LN -> attn fp16
    norm_remix_ln<<<NB*NSEQ, 256>>>(reattn, gamma, beta);
    // 4) out_h = attn @ v (2-term fp16)
    pv_gemm<<<dim3(1, 8, 64), 256>>>();
    // 5) out = g_oh @ w_out + bias (bf16 3-term, fused bias)
    out_gemm<<<dim3(8, 64), 256, SM_OUT>>>(w_out, b_out, out);
}